// round 13
// baseline (speedup 1.0000x reference)
#include <cuda_runtime.h>
#include <math.h>

#define BB 8
#define SS 1000
#define EE 1024
#define HH 16
#define DD 64
#define MM (BB*SS)        // 8000

#define TMm 128
#define TNn 128
#define TKk 16
#define NITER (EE/TKk)    // 64
#define MT ((MM + TMm - 1)/TMm)   // 63
#define STAGES 4

// Scratch (allocation-free rule: __device__ globals)
__device__ float g_q[BB*HH*SS*DD];
__device__ float g_k[BB*HH*SS*DD];
__device__ float g_v[BB*HH*SS*DD];
__device__ float g_y[BB*SS*EE];
// tf32-prerounded copies (so raw cp.async + HW truncation is lossless)
__device__ float g_x [MM*EE];
__device__ float g_wq[HH*EE*DD];
__device__ float g_wk[HH*EE*DD];
__device__ float g_wv[HH*EE*DD];
__device__ float g_wp[EE*EE];

// ---------------------------------------------------------------------------
// helpers
// ---------------------------------------------------------------------------
__device__ __forceinline__ unsigned f2tf(float f) {
    unsigned u;
    asm("cvt.rna.tf32.f32 %0, %1;" : "=r"(u) : "f"(f));
    return u;
}
__device__ __forceinline__ float f2tf_f(float f) {
    return __uint_as_float(f2tf(f));
}

__device__ __forceinline__ void mma8(float* d, const unsigned* a, const unsigned* b) {
    asm volatile(
        "mma.sync.aligned.m16n8k8.row.col.f32.tf32.tf32.f32 "
        "{%0,%1,%2,%3}, {%4,%5,%6,%7}, {%8,%9}, {%0,%1,%2,%3};"
        : "+f"(d[0]), "+f"(d[1]), "+f"(d[2]), "+f"(d[3])
        : "r"(a[0]), "r"(a[1]), "r"(a[2]), "r"(a[3]),
          "r"(b[0]), "r"(b[1]));
}

// cp.async 16B with src-size predicate (0 -> zero-fill)
__device__ __forceinline__ void cp16z(unsigned saddr, const void* gsrc, int pred16) {
    asm volatile("cp.async.cg.shared.global [%0], [%1], 16, %2;\n"
                 :: "r"(saddr), "l"(gsrc), "r"(pred16));
}
__device__ __forceinline__ void cp_commit() {
    asm volatile("cp.async.commit_group;\n" ::);
}
__device__ __forceinline__ void cp_wait2() {
    asm volatile("cp.async.wait_group 2;\n" ::);
}
__device__ __forceinline__ void cp_wait0() {
    asm volatile("cp.async.wait_group 0;\n" ::);
}

// ---------------------------------------------------------------------------
// Kernel 0: fused tf32 pre-round (RNA) of x, wq, wk, wv, wp (one launch)
// ---------------------------------------------------------------------------
#define N4_X (MM*EE/4)        // 2048000
#define N4_W (HH*EE*DD/4)     // 262144
#define N4_P (EE*EE/4)        // 262144
#define N4_TOTAL (N4_X + 3*N4_W + N4_P)

__global__ __launch_bounds__(256) void preround_all(
    const float* __restrict__ x,  const float* __restrict__ wq,
    const float* __restrict__ wk, const float* __restrict__ wv,
    const float* __restrict__ wp)
{
    int i = blockIdx.x * blockDim.x + threadIdx.x;
    const int stride = gridDim.x * blockDim.x;
    for (; i < N4_TOTAL; i += stride) {
        const float4* s;
        float* dbase;
        int off;
        if (i < N4_X)               { off = i;                  s = (const float4*)x  + off; dbase = g_x;  }
        else if (i < N4_X +   N4_W) { off = i - N4_X;           s = (const float4*)wq + off; dbase = g_wq; }
        else if (i < N4_X + 2*N4_W) { off = i - N4_X -   N4_W;  s = (const float4*)wk + off; dbase = g_wk; }
        else if (i < N4_X + 3*N4_W) { off = i - N4_X - 2*N4_W;  s = (const float4*)wv + off; dbase = g_wv; }
        else                        { off = i - N4_X - 3*N4_W;  s = (const float4*)wp + off; dbase = g_wp; }
        float4 v = *s;
        uint4 u;
        u.x = f2tf(v.x); u.y = f2tf(v.y);
        u.z = f2tf(v.z); u.w = f2tf(v.w);
        ((uint4*)dbase)[off] = u;
    }
}

// ---------------------------------------------------------------------------
// 128x128x16 TF32 GEMM core (unchanged): 8 warps (2m x 4n), 4-stage cp.async.
// ---------------------------------------------------------------------------
#define SA_WORDS 2048
#define SB_STRIDE 136
#define SB_WORDS (16*SB_STRIDE)   // 2176
#define GEMM_SMEM_WORDS (STAGES*(SA_WORDS+SB_WORDS))
#define GEMM_SMEM_BYTES (GEMM_SMEM_WORDS*4)            // 67584

struct BLQKV {
    const float* w;   // [H][E][D], pre-rounded
    int n0;
    __device__ __forceinline__ const float* addr(int k, int nq) const {
        int n = n0 + nq * 4;
        int h = n >> 6;
        int d = n & 63;
        return &w[((size_t)h * EE + k) * DD + d];
    }
};

struct BLP {
    const float* wp;  // [E, E], pre-rounded
    int n0;
    __device__ __forceinline__ const float* addr(int k, int nq) const {
        return &wp[(size_t)k * EE + n0 + nq * 4];
    }
};

template<class BL>
__device__ __forceinline__ void gemm_core(
    const float* __restrict__ Ag, int m0, const BL& bl,
    unsigned* sA, unsigned* sB, float acc[4][4][4])
{
    const int tid  = threadIdx.x;
    const int lane = tid & 31, wid = tid >> 5;
    const int g = lane >> 2, t = lane & 3;
    const int wm = wid >> 2, wn = wid & 3;

    const int arow = tid >> 1, ah = tid & 1;
    const int am   = m0 + arow;
    const int swp  = (arow >> 1) & 3;
    const int apred = (am < MM) ? 16 : 0;
    const float* asrc = Ag + (size_t)(am < MM ? am : 0) * EE + ah * 8;

    const unsigned sAu = (unsigned)__cvta_generic_to_shared(sA);
    const unsigned sBu = (unsigned)__cvta_generic_to_shared(sB);
    const unsigned ad0 = (unsigned)(arow * 16 + (((2*ah + 0) ^ swp) << 2)) * 4u;
    const unsigned ad1 = (unsigned)(arow * 16 + (((2*ah + 1) ^ swp) << 2)) * 4u;

    const int bk  = tid >> 4;
    const int bng = tid & 15;
    const unsigned bd0 = (unsigned)(bk * SB_STRIDE + bng * 4) * 4u;
    const unsigned bd1 = (unsigned)(bk * SB_STRIDE + (bng + 16) * 4) * 4u;

    #define ISSUE_AB(it, st) do {                                           \
        const float* s_ = asrc + (it) * TKk;                                \
        const unsigned ab_ = sAu + (unsigned)(st) * (SA_WORDS * 4u);        \
        cp16z(ab_ + ad0, s_, apred);                                        \
        cp16z(ab_ + ad1, s_ + 4, apred);                                    \
        const unsigned bb_ = sBu + (unsigned)(st) * (SB_WORDS * 4u);        \
        cp16z(bb_ + bd0, bl.addr((it) * TKk + bk, bng), 16);                \
        cp16z(bb_ + bd1, bl.addr((it) * TKk + bk, bng + 16), 16);           \
    } while (0)

    #define GEMM_COMPUTE(st) do {                                          \
        const unsigned* ab_ = sA + (st) * SA_WORDS;                         \
        const unsigned* bbase_ = sB + (st) * SB_WORDS;                      \
        unsigned bf[4][4];                                                  \
        _Pragma("unroll")                                                   \
        for (int nt = 0; nt < 4; nt++) {                                    \
            const unsigned* b_ = bbase_ + wn * 32 + nt * 8 + g;             \
            bf[nt][0] = b_[ t       * SB_STRIDE];                           \
            bf[nt][1] = b_[(t + 4)  * SB_STRIDE];                           \
            bf[nt][2] = b_[(t + 8)  * SB_STRIDE];                           \
            bf[nt][3] = b_[(t + 12) * SB_STRIDE];                           \
        }                                                                   \
        const int sws_ = (g >> 1) & 3;                                      \
        _Pragma("unroll")                                                   \
        for (int mt = 0; mt < 4; mt++) {                                    \
            const int r_ = wm * 64 + mt * 16 + g;                           \
            const unsigned* p1 = ab_ + r_ * 16 + t;                         \
            const unsigned* p2 = ab_ + (r_ + 8) * 16 + t;                   \
            unsigned a0_[4] = {p1[((0 ^ sws_) << 2)], p2[((0 ^ sws_) << 2)],\
                               p1[((1 ^ sws_) << 2)], p2[((1 ^ sws_) << 2)]};\
            unsigned a1_[4] = {p1[((2 ^ sws_) << 2)], p2[((2 ^ sws_) << 2)],\
                               p1[((3 ^ sws_) << 2)], p2[((3 ^ sws_) << 2)]};\
            _Pragma("unroll")                                               \
            for (int nt = 0; nt < 4; nt++) {                                \
                mma8(acc[mt][nt], a0_, &bf[nt][0]);                         \
                mma8(acc[mt][nt], a1_, &bf[nt][2]);                         \
            }                                                               \
        }                                                                   \
    } while (0)

    ISSUE_AB(0, 0); cp_commit();
    ISSUE_AB(1, 1); cp_commit();
    ISSUE_AB(2, 2); cp_commit();

    for (int it = 0; it < NITER; it++) {
        const int st = it & (STAGES - 1);
        cp_wait2();
        __syncthreads();
        GEMM_COMPUTE(st);
        if (it + 3 < NITER) ISSUE_AB(it + 3, (it + 3) & (STAGES - 1));
        cp_commit();
    }

    #undef ISSUE_AB
    #undef GEMM_COMPUTE
}

// ---------------------------------------------------------------------------
// Kernel 1: unified QKV projection (unchanged). grid = (24, 63)
// ---------------------------------------------------------------------------
__global__ __launch_bounds__(256, 2) void qkv_gemm_kernel(
    const float* __restrict__ bq, const float* __restrict__ bk_,
    const float* __restrict__ bv)
{
    extern __shared__ unsigned gsm[];
    unsigned* sA = gsm;
    unsigned* sB = gsm + STAGES * SA_WORDS;

    const int n0g   = blockIdx.x * TNn;
    const int which = n0g >> 10;
    const int n0    = n0g & 1023;
    const int m0    = blockIdx.y * TMm;

    const float* ws[3]    = {g_wq, g_wk, g_wv};
    const float* bias3[3] = {bq, bk_, bv};
    float* outs[3]        = {g_q, g_k, g_v};
    const float* bias = bias3[which];
    float* out        = outs[which];

    BLQKV bl; bl.w = ws[which]; bl.n0 = n0;

    float acc[4][4][4] = {};
    gemm_core(g_x, m0, bl, sA, sB, acc);

    const int tid  = threadIdx.x;
    const int lane = tid & 31, wid = tid >> 5;
    const int g = lane >> 2, t = lane & 3;
    const int wm = wid >> 2, wn = wid & 3;

    #pragma unroll
    for (int nt = 0; nt < 4; nt++) {
        const int nc = n0 + wn * 32 + nt * 8 + 2 * t;
        const int h  = nc >> 6;
        const int d  = nc & 63;
        const float bi0 = bias[h * DD + d];
        const float bi1 = bias[h * DD + d + 1];
        #pragma unroll
        for (int mt = 0; mt < 4; mt++) {
            #pragma unroll
            for (int half = 0; half < 2; half++) {
                const int m = m0 + wm * 64 + mt * 16 + g + half * 8;
                if (m < MM) {
                    const int b = m / SS, s = m % SS;
                    float2 r;
                    r.x = f2tf_f(acc[mt][nt][half * 2 + 0] + bi0);
                    r.y = f2tf_f(acc[mt][nt][half * 2 + 1] + bi1);
                    *(float2*)&out[((size_t)(b * HH + h) * SS + s) * DD + d] = r;
                }
            }
        }
    }
}

// ---------------------------------------------------------------------------
// Kernel 2: causal flash attention, tf32, scale = 1/sqrt(S).  BLOCK_M = 128.
// grid = (8 qtiles, 128 bh), 256 thr = 8 warps 8m x 1n (warp = 16 rows x 64 cols).
// - Q held in registers for the whole kernel (one-time strided LDG).
// - softmax fully warp-local (rows owned by one warp) -> no smem reductions.
// - PV A-fragments built from S-registers by 4-lane shuffle permute -> no psm.
// - K/V cp.async double-buffered; ONE __syncthreads per kv-tile iteration.
// smem = K 2x4352 + V 2x4608 words = 70 KB -> 2 CTAs/SM.
// ---------------------------------------------------------------------------
#define QTILES 8
#define FK_STRIDE 68
#define FV_STRIDE 72
#define FK_BUF (64*FK_STRIDE)       // 4352
#define FV_BUF (64*FV_STRIDE)       // 4608
#define F_WORDS (2*FK_BUF + 2*FV_BUF)   // 17920
#define F_BYTES (F_WORDS*4)             // 71680

__global__ __launch_bounds__(256, 2) void flash_kernel()
{
    extern __shared__ unsigned fsm[];
    unsigned* ksm = fsm;                 // 2 buffers, [row][d] stride 68
    unsigned* vsm = fsm + 2 * FK_BUF;    // 2 buffers, [row][d] stride 72

    const int qt = QTILES - 1 - blockIdx.x;   // heavy qtiles first
    const int bh = blockIdx.y;
    const int b  = bh >> 4;
    const int h  = bh & 15;

    const float* qb = g_q + (size_t)bh * SS * DD;
    const float* kb = g_k + (size_t)bh * SS * DD;
    const float* vb = g_v + (size_t)bh * SS * DD;

    const int tid  = threadIdx.x;
    const int lane = tid & 31, wid = tid >> 5;
    const int g = lane >> 2, t = lane & 3;
    const int r0 = qt * 128 + wid * 16 + g;   // global q-row, low half
    const int r1 = r0 + 8;

    const unsigned ksm_u = (unsigned)__cvta_generic_to_shared(ksm);
    const unsigned vsm_u = (unsigned)__cvta_generic_to_shared(vsm);

    const float scale = 0.031622776601683794f;  // 1/sqrt(1000)
    const float NEG_INF = __int_as_float(0xff800000);
    const int jtmax = 2 * qt + 1;

    #define ISSUE_KV(j, bf_) do {                                           \
        _Pragma("unroll")                                                   \
        for (int p = 0; p < 4; p++) {                                       \
            const int idx = p * 256 + tid;                                  \
            const int rr_ = idx >> 4;                                       \
            const int dq  = (idx & 15) * 4;                                 \
            const int gs  = (j) * 64 + rr_;                                 \
            const int pr  = (gs < SS) ? 16 : 0;                             \
            const int gc  = (gs < SS) ? gs : 0;                             \
            cp16z(ksm_u + (unsigned)((bf_) * FK_BUF + rr_ * FK_STRIDE + dq) * 4u, \
                  kb + (size_t)gc * DD + dq, pr);                           \
            cp16z(vsm_u + (unsigned)((bf_) * FV_BUF + rr_ * FV_STRIDE + dq) * 4u, \
                  vb + (size_t)gc * DD + dq, pr);                           \
        }                                                                   \
    } while (0)

    // ---- Q fragments in registers (g_q is pre-rounded tf32; raw bits exact)
    unsigned qfrag[8][4];
    {
        const unsigned* q0 = (const unsigned*)(qb + (size_t)(r0 < SS ? r0 : 0) * DD);
        const unsigned* q1 = (const unsigned*)(qb + (size_t)(r1 < SS ? r1 : 0) * DD);
        const bool v0 = (r0 < SS), v1 = (r1 < SS);
        #pragma unroll
        for (int s = 0; s < 8; s++) {
            const int c0 = 8 * s + t, c1 = c0 + 4;
            qfrag[s][0] = v0 ? q0[c0] : 0u;
            qfrag[s][1] = v1 ? q1[c0] : 0u;
            qfrag[s][2] = v0 ? q0[c1] : 0u;
            qfrag[s][3] = v1 ? q1[c1] : 0u;
        }
    }

    ISSUE_KV(0, 0);
    cp_commit();

    float oacc[8][4] = {};
    float mrow[2] = {NEG_INF, NEG_INF};
    float lrow[2] = {0.f, 0.f};

    const unsigned fullm = 0xffffffffu;
    const unsigned src0 = (lane & ~3u) | (unsigned)(t >> 1);
    const unsigned src2 = src0 + 2;

    for (int jt = 0; jt <= jtmax; jt++) {
        const int buf = jt & 1;
        cp_wait0();
        __syncthreads();   // KV(jt) visible; prev-iter reads of buf^1 done
        if (jt < jtmax) { ISSUE_KV(jt + 1, buf ^ 1); cp_commit(); }

        const unsigned* kbuf = ksm + buf * FK_BUF;
        const unsigned* vbuf = vsm + buf * FV_BUF;

        // ---- S = Q @ K^T  (8 k8-steps x 8 n-tiles)
        float sacc[8][4] = {};
        #pragma unroll
        for (int s = 0; s < 8; s++) {
            #pragma unroll
            for (int nt = 0; nt < 8; nt++) {
                const unsigned* kp = kbuf + (nt * 8 + g) * FK_STRIDE + 8 * s;
                unsigned bfr[2] = {kp[t], kp[t + 4]};
                mma8(sacc[nt], qfrag[s], bfr);
            }
        }

        // ---- scale + causal mask (only the two diagonal-adjacent kv tiles)
        if (jt >= 2 * qt) {
            #pragma unroll
            for (int nt = 0; nt < 8; nt++) {
                #pragma unroll
                for (int e = 0; e < 4; e++) {
                    const int grow = r0 + (e >> 1) * 8;
                    const int gcol = jt * 64 + nt * 8 + 2 * t + (e & 1);
                    sacc[nt][e] = (gcol > grow) ? NEG_INF : sacc[nt][e] * scale;
                }
            }
        } else {
            #pragma unroll
            for (int nt = 0; nt < 8; nt++)
                #pragma unroll
                for (int e = 0; e < 4; e++)
                    sacc[nt][e] *= scale;
        }

        // ---- warp-local online softmax; P (RNA tf32) written back into sacc
        #pragma unroll
        for (int rr = 0; rr < 2; rr++) {
            float v = NEG_INF;
            #pragma unroll
            for (int nt = 0; nt < 8; nt++)
                v = fmaxf(v, fmaxf(sacc[nt][rr * 2], sacc[nt][rr * 2 + 1]));
            v = fmaxf(v, __shfl_xor_sync(fullm, v, 1));
            v = fmaxf(v, __shfl_xor_sync(fullm, v, 2));
            const float mnew = fmaxf(mrow[rr], v);
            const float alpha = __expf(mrow[rr] - mnew);
            mrow[rr] = mnew;
            float sum = 0.f;
            #pragma unroll
            for (int nt = 0; nt < 8; nt++) {
                const float p0 = f2tf_f(__expf(sacc[nt][rr * 2]     - mnew));
                const float p1 = f2tf_f(__expf(sacc[nt][rr * 2 + 1] - mnew));
                sacc[nt][rr * 2]     = p0;
                sacc[nt][rr * 2 + 1] = p1;
                sum += p0 + p1;
                oacc[nt][rr * 2]     *= alpha;
                oacc[nt][rr * 2 + 1] *= alpha;
            }
            sum += __shfl_xor_sync(fullm, sum, 1);
            sum += __shfl_xor_sync(fullm, sum, 2);
            lrow[rr] = lrow[rr] * alpha + sum;
        }

        // ---- O += P @ V ; A-fragments from sacc via 4-lane shuffle permute
        #pragma unroll
        for (int s = 0; s < 8; s++) {
            const float a0v0 = __shfl_sync(fullm, sacc[s][0], src0);
            const float a0v1 = __shfl_sync(fullm, sacc[s][1], src0);
            const float a1v0 = __shfl_sync(fullm, sacc[s][2], src0);
            const float a1v1 = __shfl_sync(fullm, sacc[s][3], src0);
            const float a2v0 = __shfl_sync(fullm, sacc[s][0], src2);
            const float a2v1 = __shfl_sync(fullm, sacc[s][1], src2);
            const float a3v0 = __shfl_sync(fullm, sacc[s][2], src2);
            const float a3v1 = __shfl_sync(fullm, sacc[s][3], src2);
            const bool odd = (t & 1);
            unsigned afr[4];
            afr[0] = __float_as_uint(odd ? a0v1 : a0v0);
            afr[1] = __float_as_uint(odd ? a1v1 : a1v0);
            afr[2] = __float_as_uint(odd ? a2v1 : a2v0);
            afr[3] = __float_as_uint(odd ? a3v1 : a3v0);
            #pragma unroll
            for (int nt = 0; nt < 8; nt++) {
                const unsigned* vp = vbuf + (8 * s + t) * FV_STRIDE + nt * 8 + g;
                unsigned bfr[2] = {vp[0], vp[4 * FV_STRIDE]};
                mma8(oacc[nt], afr, bfr);
            }
        }
    }

    // ---- write y[b, s, h*64 + d], tf32-prerounded for proj's raw loads
    #pragma unroll
    for (int rr = 0; rr < 2; rr++) {
        const int grow = r0 + rr * 8;
        if (grow < SS) {
            const float inv = 1.f / lrow[rr];
            #pragma unroll
            for (int nt = 0; nt < 8; nt++) {
                float2 r;
                r.x = f2tf_f(oacc[nt][rr * 2]     * inv);
                r.y = f2tf_f(oacc[nt][rr * 2 + 1] * inv);
                *(float2*)&g_y[((size_t)b * SS + grow) * EE + h * DD + nt * 8 + 2 * t] = r;
            }
        }
    }
    #undef ISSUE_KV
}

// ---------------------------------------------------------------------------
// Kernel 3: out = GELU(y @ wp + bp) (unchanged). grid = (8, 63)
// ---------------------------------------------------------------------------
__global__ __launch_bounds__(256, 2) void proj_gelu_kernel(
    const float* __restrict__ bp, float* __restrict__ out)
{
    extern __shared__ unsigned gsm[];
    unsigned* sA = gsm;
    unsigned* sB = gsm + STAGES * SA_WORDS;

    const int n0 = blockIdx.x * TNn;
    const int m0 = blockIdx.y * TMm;

    BLP bl; bl.wp = g_wp; bl.n0 = n0;

    float acc[4][4][4] = {};
    gemm_core(g_y, m0, bl, sA, sB, acc);

    const int tid  = threadIdx.x;
    const int lane = tid & 31, wid = tid >> 5;
    const int g = lane >> 2, t = lane & 3;
    const int wm = wid >> 2, wn = wid & 3;

    #pragma unroll
    for (int nt = 0; nt < 4; nt++) {
        const int col = n0 + wn * 32 + nt * 8 + 2 * t;
        const float bi0 = bp[col];
        const float bi1 = bp[col + 1];
        #pragma unroll
        for (int mt = 0; mt < 4; mt++) {
            #pragma unroll
            for (int half = 0; half < 2; half++) {
                const int m = m0 + wm * 64 + mt * 16 + g + half * 8;
                if (m < MM) {
                    float t0 = acc[mt][nt][half * 2 + 0] + bi0;
                    float t1 = acc[mt][nt][half * 2 + 1] + bi1;
                    float2 r;
                    r.x = 0.5f * t0 * (1.0f + erff(t0 * 0.70710678118654752f));
                    r.y = 0.5f * t1 * (1.0f + erff(t1 * 0.70710678118654752f));
                    *(float2*)&out[(size_t)m * EE + col] = r;
                }
            }
        }
    }
}

// ---------------------------------------------------------------------------
extern "C" void kernel_launch(void* const* d_in, const int* in_sizes, int n_in,
                              void* d_out, int out_size)
{
    const float* x  = (const float*)d_in[0];
    const float* wq = (const float*)d_in[1];
    const float* bq = (const float*)d_in[2];
    const float* wk = (const float*)d_in[3];
    const float* bk = (const float*)d_in[4];
    const float* wv = (const float*)d_in[5];
    const float* bv = (const float*)d_in[6];
    const float* wp = (const float*)d_in[7];
    const float* bp = (const float*)d_in[8];
    float* out = (float*)d_out;

    cudaFuncSetAttribute(qkv_gemm_kernel,
                         cudaFuncAttributeMaxDynamicSharedMemorySize, GEMM_SMEM_BYTES);
    cudaFuncSetAttribute(proj_gelu_kernel,
                         cudaFuncAttributeMaxDynamicSharedMemorySize, GEMM_SMEM_BYTES);
    cudaFuncSetAttribute(flash_kernel,
                         cudaFuncAttributeMaxDynamicSharedMemorySize, F_BYTES);

    // Fused pre-round of inputs/weights to tf32 (RNA)
    preround_all<<<4096, 256>>>(x, wq, wk, wv, wp);

    // Unified QKV projection (tensor core TF32, 4-stage double-sided cp.async)
    dim3 g1(3 * EE / TNn, MT);     // (24, 63)
    qkv_gemm_kernel<<<g1, 256, GEMM_SMEM_BYTES>>>(bq, bk, bv);

    // Flash attention (BLOCK_M=128, warp-local softmax, register-P PV)
    dim3 g2(QTILES, BB * HH);      // (8, 128)
    flash_kernel<<<g2, 256, F_BYTES>>>();

    // Output projection + GELU
    dim3 g3(EE / TNn, MT);         // (8, 63)
    proj_gelu_kernel<<<g3, 256, GEMM_SMEM_BYTES>>>(bp, out);
}

// round 15
// speedup vs baseline: 1.4088x; 1.4088x over previous
#include <cuda_runtime.h>
#include <math.h>

#define BB 8
#define SS 1000
#define EE 1024
#define HH 16
#define DD 64
#define MM (BB*SS)        // 8000
#define STILES 16

#define TMm 128
#define TNn 128
#define TKk 16
#define NITER (EE/TKk)    // 64
#define MT ((MM + TMm - 1)/TMm)   // 63
#define STAGES 4

// Scratch (allocation-free rule: __device__ globals)
__device__ float g_q[BB*HH*SS*DD];
__device__ float g_k[BB*HH*SS*DD];
__device__ float g_v[BB*HH*SS*DD];
__device__ float g_y[BB*SS*EE];
// tf32-prerounded copies (so raw cp.async + HW truncation is lossless)
__device__ float g_x [MM*EE];
__device__ float g_wq[HH*EE*DD];
__device__ float g_wk[HH*EE*DD];
__device__ float g_wv[HH*EE*DD];
__device__ float g_wp[EE*EE];

// ---------------------------------------------------------------------------
// helpers
// ---------------------------------------------------------------------------
__device__ __forceinline__ unsigned f2tf(float f) {
    unsigned u;
    asm("cvt.rna.tf32.f32 %0, %1;" : "=r"(u) : "f"(f));
    return u;
}
__device__ __forceinline__ float f2tf_f(float f) {
    return __uint_as_float(f2tf(f));
}

__device__ __forceinline__ void mma8(float* d, const unsigned* a, const unsigned* b) {
    asm volatile(
        "mma.sync.aligned.m16n8k8.row.col.f32.tf32.tf32.f32 "
        "{%0,%1,%2,%3}, {%4,%5,%6,%7}, {%8,%9}, {%0,%1,%2,%3};"
        : "+f"(d[0]), "+f"(d[1]), "+f"(d[2]), "+f"(d[3])
        : "r"(a[0]), "r"(a[1]), "r"(a[2]), "r"(a[3]),
          "r"(b[0]), "r"(b[1]));
}

// cp.async 16B with src-size predicate (0 -> zero-fill)
__device__ __forceinline__ void cp16z(unsigned saddr, const void* gsrc, int pred16) {
    asm volatile("cp.async.cg.shared.global [%0], [%1], 16, %2;\n"
                 :: "r"(saddr), "l"(gsrc), "r"(pred16));
}
__device__ __forceinline__ void cp_commit() {
    asm volatile("cp.async.commit_group;\n" ::);
}
__device__ __forceinline__ void cp_wait2() {
    asm volatile("cp.async.wait_group 2;\n" ::);
}
__device__ __forceinline__ void cp_wait0() {
    asm volatile("cp.async.wait_group 0;\n" ::);
}

// ---------------------------------------------------------------------------
// Kernel 0: fused tf32 pre-round (RNA) of x, wq, wk, wv, wp (one launch)
// ---------------------------------------------------------------------------
#define N4_X (MM*EE/4)        // 2048000
#define N4_W (HH*EE*DD/4)     // 262144
#define N4_P (EE*EE/4)        // 262144
#define N4_TOTAL (N4_X + 3*N4_W + N4_P)

__global__ __launch_bounds__(256) void preround_all(
    const float* __restrict__ x,  const float* __restrict__ wq,
    const float* __restrict__ wk, const float* __restrict__ wv,
    const float* __restrict__ wp)
{
    int i = blockIdx.x * blockDim.x + threadIdx.x;
    const int stride = gridDim.x * blockDim.x;
    for (; i < N4_TOTAL; i += stride) {
        const float4* s;
        float* dbase;
        int off;
        if (i < N4_X)               { off = i;                  s = (const float4*)x  + off; dbase = g_x;  }
        else if (i < N4_X +   N4_W) { off = i - N4_X;           s = (const float4*)wq + off; dbase = g_wq; }
        else if (i < N4_X + 2*N4_W) { off = i - N4_X -   N4_W;  s = (const float4*)wk + off; dbase = g_wk; }
        else if (i < N4_X + 3*N4_W) { off = i - N4_X - 2*N4_W;  s = (const float4*)wv + off; dbase = g_wv; }
        else                        { off = i - N4_X - 3*N4_W;  s = (const float4*)wp + off; dbase = g_wp; }
        float4 v = *s;
        uint4 u;
        u.x = f2tf(v.x); u.y = f2tf(v.y);
        u.z = f2tf(v.z); u.w = f2tf(v.w);
        ((uint4*)dbase)[off] = u;
    }
}

// ---------------------------------------------------------------------------
// 128x128x16 TF32 GEMM core: 8 warps (2m x 4n), 4-stage cp.async (A and B).
// All sources pre-rounded tf32 -> HW truncation inside HMMA.tf32 is exact.
// ---------------------------------------------------------------------------
#define SA_WORDS 2048
#define SB_STRIDE 136
#define SB_WORDS (16*SB_STRIDE)   // 2176
#define GEMM_SMEM_WORDS (STAGES*(SA_WORDS+SB_WORDS))
#define GEMM_SMEM_BYTES (GEMM_SMEM_WORDS*4)            // 67584

struct BLQKV {
    const float* w;   // [H][E][D], pre-rounded
    int n0;
    __device__ __forceinline__ const float* addr(int k, int nq) const {
        int n = n0 + nq * 4;
        int h = n >> 6;
        int d = n & 63;
        return &w[((size_t)h * EE + k) * DD + d];
    }
};

struct BLP {
    const float* wp;  // [E, E], pre-rounded
    int n0;
    __device__ __forceinline__ const float* addr(int k, int nq) const {
        return &wp[(size_t)k * EE + n0 + nq * 4];
    }
};

template<class BL>
__device__ __forceinline__ void gemm_core(
    const float* __restrict__ Ag, int m0, const BL& bl,
    unsigned* sA, unsigned* sB, float acc[4][4][4])
{
    const int tid  = threadIdx.x;
    const int lane = tid & 31, wid = tid >> 5;
    const int g = lane >> 2, t = lane & 3;
    const int wm = wid >> 2, wn = wid & 3;

    const int arow = tid >> 1, ah = tid & 1;
    const int am   = m0 + arow;
    const int swp  = (arow >> 1) & 3;
    const int apred = (am < MM) ? 16 : 0;
    const float* asrc = Ag + (size_t)(am < MM ? am : 0) * EE + ah * 8;

    const unsigned sAu = (unsigned)__cvta_generic_to_shared(sA);
    const unsigned sBu = (unsigned)__cvta_generic_to_shared(sB);
    const unsigned ad0 = (unsigned)(arow * 16 + (((2*ah + 0) ^ swp) << 2)) * 4u;
    const unsigned ad1 = (unsigned)(arow * 16 + (((2*ah + 1) ^ swp) << 2)) * 4u;

    const int bk  = tid >> 4;
    const int bng = tid & 15;
    const unsigned bd0 = (unsigned)(bk * SB_STRIDE + bng * 4) * 4u;
    const unsigned bd1 = (unsigned)(bk * SB_STRIDE + (bng + 16) * 4) * 4u;

    #define ISSUE_AB(it, st) do {                                           \
        const float* s_ = asrc + (it) * TKk;                                \
        const unsigned ab_ = sAu + (unsigned)(st) * (SA_WORDS * 4u);        \
        cp16z(ab_ + ad0, s_, apred);                                        \
        cp16z(ab_ + ad1, s_ + 4, apred);                                    \
        const unsigned bb_ = sBu + (unsigned)(st) * (SB_WORDS * 4u);        \
        cp16z(bb_ + bd0, bl.addr((it) * TKk + bk, bng), 16);                \
        cp16z(bb_ + bd1, bl.addr((it) * TKk + bk, bng + 16), 16);           \
    } while (0)

    #define GEMM_COMPUTE(st) do {                                          \
        const unsigned* ab_ = sA + (st) * SA_WORDS;                         \
        const unsigned* bbase_ = sB + (st) * SB_WORDS;                      \
        unsigned bf[4][4];                                                  \
        _Pragma("unroll")                                                   \
        for (int nt = 0; nt < 4; nt++) {                                    \
            const unsigned* b_ = bbase_ + wn * 32 + nt * 8 + g;             \
            bf[nt][0] = b_[ t       * SB_STRIDE];                           \
            bf[nt][1] = b_[(t + 4)  * SB_STRIDE];                           \
            bf[nt][2] = b_[(t + 8)  * SB_STRIDE];                           \
            bf[nt][3] = b_[(t + 12) * SB_STRIDE];                           \
        }                                                                   \
        const int sws_ = (g >> 1) & 3;                                      \
        _Pragma("unroll")                                                   \
        for (int mt = 0; mt < 4; mt++) {                                    \
            const int r_ = wm * 64 + mt * 16 + g;                           \
            const unsigned* p1 = ab_ + r_ * 16 + t;                         \
            const unsigned* p2 = ab_ + (r_ + 8) * 16 + t;                   \
            unsigned a0_[4] = {p1[((0 ^ sws_) << 2)], p2[((0 ^ sws_) << 2)],\
                               p1[((1 ^ sws_) << 2)], p2[((1 ^ sws_) << 2)]};\
            unsigned a1_[4] = {p1[((2 ^ sws_) << 2)], p2[((2 ^ sws_) << 2)],\
                               p1[((3 ^ sws_) << 2)], p2[((3 ^ sws_) << 2)]};\
            _Pragma("unroll")                                               \
            for (int nt = 0; nt < 4; nt++) {                                \
                mma8(acc[mt][nt], a0_, &bf[nt][0]);                         \
                mma8(acc[mt][nt], a1_, &bf[nt][2]);                         \
            }                                                               \
        }                                                                   \
    } while (0)

    ISSUE_AB(0, 0); cp_commit();
    ISSUE_AB(1, 1); cp_commit();
    ISSUE_AB(2, 2); cp_commit();

    for (int it = 0; it < NITER; it++) {
        const int st = it & (STAGES - 1);
        cp_wait2();
        __syncthreads();
        GEMM_COMPUTE(st);
        if (it + 3 < NITER) ISSUE_AB(it + 3, (it + 3) & (STAGES - 1));
        cp_commit();
    }

    #undef ISSUE_AB
    #undef GEMM_COMPUTE
}

// ---------------------------------------------------------------------------
// Kernel 1: unified QKV projection. grid = (24 ntiles over 3072, 63 mtiles)
// ---------------------------------------------------------------------------
__global__ __launch_bounds__(256, 2) void qkv_gemm_kernel(
    const float* __restrict__ bq, const float* __restrict__ bk_,
    const float* __restrict__ bv)
{
    extern __shared__ unsigned gsm[];
    unsigned* sA = gsm;
    unsigned* sB = gsm + STAGES * SA_WORDS;

    const int n0g   = blockIdx.x * TNn;
    const int which = n0g >> 10;
    const int n0    = n0g & 1023;
    const int m0    = blockIdx.y * TMm;

    const float* ws[3]    = {g_wq, g_wk, g_wv};
    const float* bias3[3] = {bq, bk_, bv};
    float* outs[3]        = {g_q, g_k, g_v};
    const float* bias = bias3[which];
    float* out        = outs[which];

    BLQKV bl; bl.w = ws[which]; bl.n0 = n0;

    float acc[4][4][4] = {};
    gemm_core(g_x, m0, bl, sA, sB, acc);

    const int tid  = threadIdx.x;
    const int lane = tid & 31, wid = tid >> 5;
    const int g = lane >> 2, t = lane & 3;
    const int wm = wid >> 2, wn = wid & 3;

    #pragma unroll
    for (int nt = 0; nt < 4; nt++) {
        const int nc = n0 + wn * 32 + nt * 8 + 2 * t;
        const int h  = nc >> 6;
        const int d  = nc & 63;
        const float bi0 = bias[h * DD + d];
        const float bi1 = bias[h * DD + d + 1];
        #pragma unroll
        for (int mt = 0; mt < 4; mt++) {
            #pragma unroll
            for (int half = 0; half < 2; half++) {
                const int m = m0 + wm * 64 + mt * 16 + g + half * 8;
                if (m < MM) {
                    const int b = m / SS, s = m % SS;
                    float2 r;
                    r.x = f2tf_f(acc[mt][nt][half * 2 + 0] + bi0);
                    r.y = f2tf_f(acc[mt][nt][half * 2 + 1] + bi1);
                    *(float2*)&out[((size_t)(b * HH + h) * SS + s) * DD + d] = r;
                }
            }
        }
    }
}

// ---------------------------------------------------------------------------
// Kernel 2: causal flash attention on tensor cores (tf32), scale = 1/sqrt(S).
// grid = (16 qtiles reversed, 128 bh), 256 threads = 8 warps (4m x 2n),
// warp = 16x32. (Round-12 proven version; only the qtile order changed.)
// ---------------------------------------------------------------------------
#define F_KSM 4096
#define F_VSM 12800
#define F_PSM 22016
#define F_REDM 26112
#define F_REDS 26240
#define F_WORDS 26368
#define F_BYTES (F_WORDS*4)

__global__ __launch_bounds__(256, 2) void flash_kernel()
{
    extern __shared__ unsigned fsm[];
    unsigned* qsm = fsm;
    unsigned* ksm = fsm + F_KSM;     // 2 bufs, stride 4352 ([seq][d] stride 68)
    unsigned* vsm = fsm + F_VSM;     // 2 bufs, stride 4608 ([seq][d] stride 72)
    unsigned* psm = fsm + F_PSM;
    float* redm   = (float*)(fsm + F_REDM);   // [2][64]
    float* reds   = (float*)(fsm + F_REDS);   // [2][64]

    const int qt = STILES - 1 - blockIdx.x;   // heavy qtiles first
    const int bh = blockIdx.y;
    const int b  = bh >> 4;
    const int h  = bh & 15;

    const float* qb = g_q + (size_t)bh * SS * DD;
    const float* kb = g_k + (size_t)bh * SS * DD;
    const float* vb = g_v + (size_t)bh * SS * DD;

    const int tid  = threadIdx.x;
    const int lane = tid & 31, wid = tid >> 5;
    const int g = lane >> 2, t = lane & 3;
    const int wm2 = wid >> 1, wn2 = wid & 1;
    const int r0  = wm2 * 16 + g;
    const int swL = (r0 >> 1) & 3;
    const int swH = ((r0 + 8) >> 1) & 3;

    const unsigned kbase_u = (unsigned)__cvta_generic_to_shared(ksm);
    const unsigned vbase_u = (unsigned)__cvta_generic_to_shared(vsm);

    const float scale = 0.031622776601683794f;  // 1/sqrt(1000)
    const float NEG_INF = __int_as_float(0xff800000);

    #define ISSUE_KV(j, bf_) do {                                           \
        _Pragma("unroll")                                                   \
        for (int p = 0; p < 4; p++) {                                       \
            const int idx = p * 256 + tid;                                  \
            const int rr  = idx >> 4;                                       \
            const int dq  = (idx & 15) * 4;                                 \
            const int gs  = (j) * 64 + rr;                                  \
            const int pr  = (gs < SS) ? 16 : 0;                             \
            const int gc  = (gs < SS) ? gs : 0;                             \
            cp16z(kbase_u + (unsigned)((bf_) * 4352 + rr * 68 + dq) * 4u,   \
                  kb + (size_t)gc * DD + dq, pr);                           \
            cp16z(vbase_u + (unsigned)((bf_) * 4608 + rr * 72 + dq) * 4u,   \
                  vb + (size_t)gc * DD + dq, pr);                           \
        }                                                                   \
    } while (0)

    // ---- Q fill (raw bits: g_q is pre-rounded tf32)
    {
        const int row = tid >> 2, slab = tid & 3;
        const int gs = qt * 64 + row;
        unsigned f[16];
        if (gs < SS) {
            const float* p = qb + (size_t)gs * DD + slab * 16;
            #pragma unroll
            for (int q = 0; q < 4; q++) {
                uint4 v = *(const uint4*)(p + q * 4);
                f[q*4+0]=v.x; f[q*4+1]=v.y; f[q*4+2]=v.z; f[q*4+3]=v.w;
            }
        } else {
            #pragma unroll
            for (int i = 0; i < 16; i++) f[i] = 0u;
        }
        const int sw = (row >> 1) & 3;
        unsigned* base = qsm + (row * 4 + slab) * 16;
        #pragma unroll
        for (int c = 0; c < 4; c++) {
            uint4 u;
            u.x = f[c];     u.y = f[4 + c];
            u.z = f[8 + c]; u.w = f[12 + c];
            *(uint4*)(base + ((c ^ sw) << 2)) = u;
        }
    }

    // prefetch KV(0)
    ISSUE_KV(0, 0);
    cp_commit();

    float oacc[4][4] = {};
    float mrow[2] = {NEG_INF, NEG_INF};
    float lrow[2] = {0.f, 0.f};

    for (int jt = 0; jt <= qt; jt++) {
        const int buf = jt & 1;
        cp_wait0();
        __syncthreads();   // KV(jt) visible; guards psm/red/Q and buf reuse
        if (jt < qt) { ISSUE_KV(jt + 1, buf ^ 1); cp_commit(); }

        const unsigned* kbuf = ksm + buf * 4352;
        const unsigned* vbuf = vsm + buf * 4608;

        // ---- S = Q @ K^T
        float sacc[4][4] = {};
        #pragma unroll
        for (int s = 0; s < 4; s++) {
            uint4 alo = *(const uint4*)(qsm + (r0 * 4 + s) * 16 + ((t ^ swL) << 2));
            uint4 ahi = *(const uint4*)(qsm + ((r0 + 8) * 4 + s) * 16 + ((t ^ swH) << 2));
            unsigned a1[4] = {alo.x, ahi.x, alo.y, ahi.y};
            unsigned a2[4] = {alo.z, ahi.z, alo.w, ahi.w};
            #pragma unroll
            for (int nt = 0; nt < 4; nt++) {
                const int col = wn2 * 32 + nt * 8 + g;
                const unsigned* kp = kbuf + col * 68 + s * 16;
                unsigned b1[2] = {kp[t],     kp[t + 4]};
                unsigned b2[2] = {kp[t + 8], kp[t + 12]};
                mma8(sacc[nt], a1, b1);
                mma8(sacc[nt], a2, b2);
            }
        }

        // ---- scale + causal mask (diagonal tile only)
        if (jt == qt) {
            #pragma unroll
            for (int nt = 0; nt < 4; nt++) {
                #pragma unroll
                for (int e = 0; e < 4; e++) {
                    const int grow = qt * 64 + r0 + (e >> 1) * 8;
                    const int gcol = jt * 64 + wn2 * 32 + nt * 8 + 2 * t + (e & 1);
                    sacc[nt][e] = (gcol > grow || gcol >= SS) ? NEG_INF
                                                              : sacc[nt][e] * scale;
                }
            }
        } else {
            #pragma unroll
            for (int nt = 0; nt < 4; nt++)
                #pragma unroll
                for (int e = 0; e < 4; e++)
                    sacc[nt][e] *= scale;
        }

        // ---- row max (warp part), cross-warp via smem
        #pragma unroll
        for (int rr = 0; rr < 2; rr++) {
            float v = fmaxf(fmaxf(sacc[0][rr*2], sacc[0][rr*2+1]),
                            fmaxf(sacc[1][rr*2], sacc[1][rr*2+1]));
            v = fmaxf(v, fmaxf(fmaxf(sacc[2][rr*2], sacc[2][rr*2+1]),
                               fmaxf(sacc[3][rr*2], sacc[3][rr*2+1])));
            v = fmaxf(v, __shfl_xor_sync(0xffffffffu, v, 1));
            v = fmaxf(v, __shfl_xor_sync(0xffffffffu, v, 2));
            if (t == 0) redm[wn2 * 64 + r0 + rr * 8] = v;
        }
        __syncthreads();

        // ---- exp, P -> psm (RNA, A-layout), partial sums, rescale O
        float alpha[2];
        #pragma unroll
        for (int rr = 0; rr < 2; rr++) {
            const int rl = r0 + rr * 8;
            const float mtile = fmaxf(redm[rl], redm[64 + rl]);
            const float mnew  = fmaxf(mrow[rr], mtile);
            alpha[rr] = __expf(mrow[rr] - mnew);
            mrow[rr]  = mnew;
            float sum = 0.f;
            const int sw = (rl >> 1) & 3;
            unsigned* pbase = psm + rl * 64;
            #pragma unroll
            for (int nt = 0; nt < 4; nt++) {
                #pragma unroll
                for (int e = 0; e < 2; e++) {
                    const float pv = __expf(sacc[nt][rr * 2 + e] - mnew);
                    sum += pv;
                    const int col  = wn2 * 32 + nt * 8 + 2 * t + e;
                    const int slab = col >> 4, cc = col & 3, j = (col >> 2) & 3;
                    pbase[slab * 16 + ((cc ^ sw) << 2) + j] = f2tf(pv);
                }
                oacc[nt][rr * 2]     *= alpha[rr];
                oacc[nt][rr * 2 + 1] *= alpha[rr];
            }
            sum += __shfl_xor_sync(0xffffffffu, sum, 1);
            sum += __shfl_xor_sync(0xffffffffu, sum, 2);
            if (t == 0) reds[wn2 * 64 + rl] = sum;
        }
        __syncthreads();

        #pragma unroll
        for (int rr = 0; rr < 2; rr++) {
            const int rl = r0 + rr * 8;
            lrow[rr] = lrow[rr] * alpha[rr] + reds[rl] + reds[64 + rl];
        }

        // ---- O += P @ V
        #pragma unroll
        for (int s = 0; s < 4; s++) {
            uint4 alo = *(const uint4*)(psm + (r0 * 4 + s) * 16 + ((t ^ swL) << 2));
            uint4 ahi = *(const uint4*)(psm + ((r0 + 8) * 4 + s) * 16 + ((t ^ swH) << 2));
            unsigned a1[4] = {alo.x, ahi.x, alo.y, ahi.y};
            unsigned a2[4] = {alo.z, ahi.z, alo.w, ahi.w};
            #pragma unroll
            for (int nt = 0; nt < 4; nt++) {
                const int col = wn2 * 32 + nt * 8 + g;
                const unsigned* vp = vbuf + (s * 16) * 72 + col;
                unsigned b1[2] = {vp[t * 72],       vp[(t + 4) * 72]};
                unsigned b2[2] = {vp[(t + 8) * 72], vp[(t + 12) * 72]};
                mma8(oacc[nt], a1, b1);
                mma8(oacc[nt], a2, b2);
            }
        }
    }

    // ---- write y[b, s, h*64 + d], tf32-prerounded for proj's raw loads
    #pragma unroll
    for (int rr = 0; rr < 2; rr++) {
        const int grow = qt * 64 + r0 + rr * 8;
        if (grow < SS) {
            const float inv = 1.f / lrow[rr];
            #pragma unroll
            for (int nt = 0; nt < 4; nt++) {
                float2 r;
                r.x = f2tf_f(oacc[nt][rr * 2]     * inv);
                r.y = f2tf_f(oacc[nt][rr * 2 + 1] * inv);
                const int col = wn2 * 32 + nt * 8 + 2 * t;
                *(float2*)&g_y[((size_t)b * SS + grow) * EE + h * DD + col] = r;
            }
        }
    }
    #undef ISSUE_KV
}

// ---------------------------------------------------------------------------
// Kernel 3: out = GELU(y @ wp + bp). grid = (8 ntiles, 63 mtiles)
// ---------------------------------------------------------------------------
__global__ __launch_bounds__(256, 2) void proj_gelu_kernel(
    const float* __restrict__ bp, float* __restrict__ out)
{
    extern __shared__ unsigned gsm[];
    unsigned* sA = gsm;
    unsigned* sB = gsm + STAGES * SA_WORDS;

    const int n0 = blockIdx.x * TNn;
    const int m0 = blockIdx.y * TMm;

    BLP bl; bl.wp = g_wp; bl.n0 = n0;

    float acc[4][4][4] = {};
    gemm_core(g_y, m0, bl, sA, sB, acc);

    const int tid  = threadIdx.x;
    const int lane = tid & 31, wid = tid >> 5;
    const int g = lane >> 2, t = lane & 3;
    const int wm = wid >> 2, wn = wid & 3;

    #pragma unroll
    for (int nt = 0; nt < 4; nt++) {
        const int col = n0 + wn * 32 + nt * 8 + 2 * t;
        const float bi0 = bp[col];
        const float bi1 = bp[col + 1];
        #pragma unroll
        for (int mt = 0; mt < 4; mt++) {
            #pragma unroll
            for (int half = 0; half < 2; half++) {
                const int m = m0 + wm * 64 + mt * 16 + g + half * 8;
                if (m < MM) {
                    float t0 = acc[mt][nt][half * 2 + 0] + bi0;
                    float t1 = acc[mt][nt][half * 2 + 1] + bi1;
                    float2 r;
                    r.x = 0.5f * t0 * (1.0f + erff(t0 * 0.70710678118654752f));
                    r.y = 0.5f * t1 * (1.0f + erff(t1 * 0.70710678118654752f));
                    *(float2*)&out[(size_t)m * EE + col] = r;
                }
            }
        }
    }
}

// ---------------------------------------------------------------------------
extern "C" void kernel_launch(void* const* d_in, const int* in_sizes, int n_in,
                              void* d_out, int out_size)
{
    const float* x  = (const float*)d_in[0];
    const float* wq = (const float*)d_in[1];
    const float* bq = (const float*)d_in[2];
    const float* wk = (const float*)d_in[3];
    const float* bk = (const float*)d_in[4];
    const float* wv = (const float*)d_in[5];
    const float* bv = (const float*)d_in[6];
    const float* wp = (const float*)d_in[7];
    const float* bp = (const float*)d_in[8];
    float* out = (float*)d_out;

    cudaFuncSetAttribute(qkv_gemm_kernel,
                         cudaFuncAttributeMaxDynamicSharedMemorySize, GEMM_SMEM_BYTES);
    cudaFuncSetAttribute(proj_gelu_kernel,
                         cudaFuncAttributeMaxDynamicSharedMemorySize, GEMM_SMEM_BYTES);
    cudaFuncSetAttribute(flash_kernel,
                         cudaFuncAttributeMaxDynamicSharedMemorySize, F_BYTES);

    // Fused pre-round of inputs/weights to tf32 (RNA), one launch
    preround_all<<<4096, 256>>>(x, wq, wk, wv, wp);

    // Unified QKV projection (tensor core TF32, 4-stage double-sided cp.async)
    dim3 g1(3 * EE / TNn, MT);     // (24, 63)
    qkv_gemm_kernel<<<g1, 256, GEMM_SMEM_BYTES>>>(bq, bk, bv);

    // Flash attention (round-12 version, heavy qtiles scheduled first)
    dim3 g2(STILES, BB * HH);      // (16, 128)
    flash_kernel<<<g2, 256, F_BYTES>>>();

    // Output projection + GELU
    dim3 g3(EE / TNn, MT);         // (8, 63)
    proj_gelu_kernel<<<g3, 256, GEMM_SMEM_BYTES>>>(bp, out);
}

// round 16
// speedup vs baseline: 1.4269x; 1.0128x over previous
#include <cuda_runtime.h>
#include <math.h>

#define BB 8
#define SS 1000
#define EE 1024
#define HH 16
#define DD 64
#define MM (BB*SS)        // 8000
#define STILES 16

#define TMm 128
#define TNn 128
#define TKk 32
#define NITER (EE/TKk)    // 32
#define MT ((MM + TMm - 1)/TMm)   // 63
#define STAGES 3

// Scratch (allocation-free rule: __device__ globals)
__device__ float g_q[BB*HH*SS*DD];
__device__ float g_k[BB*HH*SS*DD];
__device__ float g_v[BB*HH*SS*DD];
__device__ float g_y[BB*SS*EE];
// tf32-prerounded copies (so raw cp.async + HW truncation is lossless)
__device__ float g_x [MM*EE];
__device__ float g_wq[HH*EE*DD];
__device__ float g_wk[HH*EE*DD];
__device__ float g_wv[HH*EE*DD];
__device__ float g_wp[EE*EE];

// ---------------------------------------------------------------------------
// helpers
// ---------------------------------------------------------------------------
__device__ __forceinline__ unsigned f2tf(float f) {
    unsigned u;
    asm("cvt.rna.tf32.f32 %0, %1;" : "=r"(u) : "f"(f));
    return u;
}
__device__ __forceinline__ float f2tf_f(float f) {
    return __uint_as_float(f2tf(f));
}

__device__ __forceinline__ void mma8(float* d, const unsigned* a, const unsigned* b) {
    asm volatile(
        "mma.sync.aligned.m16n8k8.row.col.f32.tf32.tf32.f32 "
        "{%0,%1,%2,%3}, {%4,%5,%6,%7}, {%8,%9}, {%0,%1,%2,%3};"
        : "+f"(d[0]), "+f"(d[1]), "+f"(d[2]), "+f"(d[3])
        : "r"(a[0]), "r"(a[1]), "r"(a[2]), "r"(a[3]),
          "r"(b[0]), "r"(b[1]));
}

// cp.async 16B with src-size predicate (0 -> zero-fill)
__device__ __forceinline__ void cp16z(unsigned saddr, const void* gsrc, int pred16) {
    asm volatile("cp.async.cg.shared.global [%0], [%1], 16, %2;\n"
                 :: "r"(saddr), "l"(gsrc), "r"(pred16));
}
__device__ __forceinline__ void cp_commit() {
    asm volatile("cp.async.commit_group;\n" ::);
}
__device__ __forceinline__ void cp_wait1() {
    asm volatile("cp.async.wait_group 1;\n" ::);
}
__device__ __forceinline__ void cp_wait0() {
    asm volatile("cp.async.wait_group 0;\n" ::);
}

// ---------------------------------------------------------------------------
// Kernel 0: fused tf32 pre-round (RNA) of x, wq, wk, wv, wp (one launch)
// ---------------------------------------------------------------------------
#define N4_X (MM*EE/4)        // 2048000
#define N4_W (HH*EE*DD/4)     // 262144
#define N4_P (EE*EE/4)        // 262144
#define N4_TOTAL (N4_X + 3*N4_W + N4_P)

__global__ __launch_bounds__(256) void preround_all(
    const float* __restrict__ x,  const float* __restrict__ wq,
    const float* __restrict__ wk, const float* __restrict__ wv,
    const float* __restrict__ wp)
{
    int i = blockIdx.x * blockDim.x + threadIdx.x;
    const int stride = gridDim.x * blockDim.x;
    for (; i < N4_TOTAL; i += stride) {
        const float4* s;
        float* dbase;
        int off;
        if (i < N4_X)               { off = i;                  s = (const float4*)x  + off; dbase = g_x;  }
        else if (i < N4_X +   N4_W) { off = i - N4_X;           s = (const float4*)wq + off; dbase = g_wq; }
        else if (i < N4_X + 2*N4_W) { off = i - N4_X -   N4_W;  s = (const float4*)wk + off; dbase = g_wk; }
        else if (i < N4_X + 3*N4_W) { off = i - N4_X - 2*N4_W;  s = (const float4*)wv + off; dbase = g_wv; }
        else                        { off = i - N4_X - 3*N4_W;  s = (const float4*)wp + off; dbase = g_wp; }
        float4 v = *s;
        uint4 u;
        u.x = f2tf(v.x); u.y = f2tf(v.y);
        u.z = f2tf(v.z); u.w = f2tf(v.w);
        ((uint4*)dbase)[off] = u;
    }
}

// ---------------------------------------------------------------------------
// 128x128x32 TF32 GEMM core: 8 warps (2m x 4n), 3-stage cp.async (A and B).
// All sources pre-rounded tf32 -> HW truncation inside HMMA.tf32 is exact.
//
// sA (per stage, 4096 words): word = row*32 + (((k>>2) ^ sw3(row))<<2) + (k&3),
//   sw3(row) = ((row>>1)&3) | ((row&1)<<2). Chunks are k-contiguous 16B ->
//   cp.async-fillable; fragment scalar LDS hit all 32 banks (8 distinct chunk
//   positions across g-lanes x 4 t-banks).
// sB (per stage, 32*136 words): [k][n] stride 136 (==8 mod 32 -> scalar
//   fragment loads conflict-free).
// MMA order per accumulator identical to the TKk=16 core -> bitwise-same result.
// ---------------------------------------------------------------------------
#define SA_WORDS 4096
#define SB_STRIDE 136
#define SB_WORDS (32*SB_STRIDE)   // 4352
#define GEMM_SMEM_WORDS (STAGES*(SA_WORDS+SB_WORDS))   // 25344
#define GEMM_SMEM_BYTES (GEMM_SMEM_WORDS*4)            // 101376

struct BLQKV {
    const float* w;   // [H][E][D], pre-rounded
    int n0;
    __device__ __forceinline__ const float* addr(int k, int nq) const {
        int n = n0 + nq * 4;
        int h = n >> 6;
        int d = n & 63;
        return &w[((size_t)h * EE + k) * DD + d];
    }
};

struct BLP {
    const float* wp;  // [E, E], pre-rounded
    int n0;
    __device__ __forceinline__ const float* addr(int k, int nq) const {
        return &wp[(size_t)k * EE + n0 + nq * 4];
    }
};

template<class BL>
__device__ __forceinline__ void gemm_core(
    const float* __restrict__ Ag, int m0, const BL& bl,
    unsigned* sA, unsigned* sB, float acc[4][4][4])
{
    const int tid  = threadIdx.x;
    const int lane = tid & 31, wid = tid >> 5;
    const int g = lane >> 2, t = lane & 3;
    const int wm = wid >> 2, wn = wid & 3;

    // A producer: thread -> (row = tid>>1, half ah = tid&1), 4 x 16B chunks
    const int arow = tid >> 1, ah = tid & 1;
    const int am   = m0 + arow;
    const int sw3p = ((arow >> 1) & 3) | ((arow & 1) << 2);
    const int apred = (am < MM) ? 16 : 0;
    const float* asrc = Ag + (size_t)(am < MM ? am : 0) * EE + ah * 16;

    const unsigned sAu = (unsigned)__cvta_generic_to_shared(sA);
    const unsigned sBu = (unsigned)__cvta_generic_to_shared(sB);
    unsigned adst[4];
    #pragma unroll
    for (int j = 0; j < 4; j++)
        adst[j] = (unsigned)(arow * 32 + ((((ah << 2) + j) ^ sw3p) << 2)) * 4u;

    // B producer: thread -> (k = tid>>3, n-quads tid&7 + {0,8,16,24})
    const int bk  = tid >> 3;
    const int bq0 = tid & 7;
    unsigned bdst[4];
    #pragma unroll
    for (int q = 0; q < 4; q++)
        bdst[q] = (unsigned)(bk * SB_STRIDE + (bq0 + 8 * q) * 4) * 4u;

    #define ISSUE_AB(it, st) do {                                           \
        const float* s_ = asrc + (it) * TKk;                                \
        const unsigned ab_ = sAu + (unsigned)(st) * (SA_WORDS * 4u);        \
        _Pragma("unroll")                                                   \
        for (int j = 0; j < 4; j++)                                         \
            cp16z(ab_ + adst[j], s_ + 4 * j, apred);                        \
        const unsigned bb_ = sBu + (unsigned)(st) * (SB_WORDS * 4u);        \
        _Pragma("unroll")                                                   \
        for (int q = 0; q < 4; q++)                                         \
            cp16z(bb_ + bdst[q], bl.addr((it) * TKk + bk, bq0 + 8 * q), 16);\
    } while (0)

    #define GEMM_COMPUTE(st) do {                                          \
        const unsigned* ab_ = sA + (st) * SA_WORDS;                         \
        const unsigned* bbase_ = sB + (st) * SB_WORDS;                      \
        _Pragma("unroll")                                                   \
        for (int s = 0; s < 4; s++) {                                       \
            unsigned bf[4][2];                                              \
            _Pragma("unroll")                                               \
            for (int nt = 0; nt < 4; nt++) {                                \
                const unsigned* b_ = bbase_ + wn * 32 + nt * 8 + g;         \
                bf[nt][0] = b_[(8 * s + t)     * SB_STRIDE];                \
                bf[nt][1] = b_[(8 * s + t + 4) * SB_STRIDE];                \
            }                                                               \
            _Pragma("unroll")                                               \
            for (int mt = 0; mt < 4; mt++) {                                \
                const int r_ = wm * 64 + mt * 16 + g;                       \
                const int sw3_ = ((r_ >> 1) & 3) | ((r_ & 1) << 2);         \
                const unsigned* p1 = ab_ + r_ * 32 + t;                     \
                const unsigned* p2 = p1 + 8 * 32;                           \
                const int c0 = (((2 * s)     ^ sw3_) << 2);                 \
                const int c1 = (((2 * s + 1) ^ sw3_) << 2);                 \
                unsigned a_[4] = {p1[c0], p2[c0], p1[c1], p2[c1]};          \
                _Pragma("unroll")                                           \
                for (int nt = 0; nt < 4; nt++)                              \
                    mma8(acc[mt][nt], a_, bf[nt]);                          \
            }                                                               \
        }                                                                   \
    } while (0)

    // prologue: 2 stages in flight
    ISSUE_AB(0, 0); cp_commit();
    ISSUE_AB(1, 1); cp_commit();

    int st = 0;
    for (int it = 0; it < NITER; it++) {
        cp_wait1();
        __syncthreads();             // stage(it) visible to all warps
        GEMM_COMPUTE(st);
        if (it + 2 < NITER) {
            int st2 = st + 2; if (st2 >= STAGES) st2 -= STAGES;
            ISSUE_AB(it + 2, st2);
        }
        cp_commit();                 // possibly-empty group keeps wait count
        if (++st == STAGES) st = 0;
    }

    #undef ISSUE_AB
    #undef GEMM_COMPUTE
}

// ---------------------------------------------------------------------------
// Kernel 1: unified QKV projection. grid = (24 ntiles over 3072, 63 mtiles)
// ---------------------------------------------------------------------------
__global__ __launch_bounds__(256, 2) void qkv_gemm_kernel(
    const float* __restrict__ bq, const float* __restrict__ bk_,
    const float* __restrict__ bv)
{
    extern __shared__ unsigned gsm[];
    unsigned* sA = gsm;
    unsigned* sB = gsm + STAGES * SA_WORDS;

    const int n0g   = blockIdx.x * TNn;
    const int which = n0g >> 10;
    const int n0    = n0g & 1023;
    const int m0    = blockIdx.y * TMm;

    const float* ws[3]    = {g_wq, g_wk, g_wv};
    const float* bias3[3] = {bq, bk_, bv};
    float* outs[3]        = {g_q, g_k, g_v};
    const float* bias = bias3[which];
    float* out        = outs[which];

    BLQKV bl; bl.w = ws[which]; bl.n0 = n0;

    float acc[4][4][4] = {};
    gemm_core(g_x, m0, bl, sA, sB, acc);

    const int tid  = threadIdx.x;
    const int lane = tid & 31, wid = tid >> 5;
    const int g = lane >> 2, t = lane & 3;
    const int wm = wid >> 2, wn = wid & 3;

    #pragma unroll
    for (int nt = 0; nt < 4; nt++) {
        const int nc = n0 + wn * 32 + nt * 8 + 2 * t;
        const int h  = nc >> 6;
        const int d  = nc & 63;
        const float bi0 = bias[h * DD + d];
        const float bi1 = bias[h * DD + d + 1];
        #pragma unroll
        for (int mt = 0; mt < 4; mt++) {
            #pragma unroll
            for (int half = 0; half < 2; half++) {
                const int m = m0 + wm * 64 + mt * 16 + g + half * 8;
                if (m < MM) {
                    const int b = m / SS, s = m % SS;
                    float2 r;
                    r.x = f2tf_f(acc[mt][nt][half * 2 + 0] + bi0);
                    r.y = f2tf_f(acc[mt][nt][half * 2 + 1] + bi1);
                    *(float2*)&out[((size_t)(b * HH + h) * SS + s) * DD + d] = r;
                }
            }
        }
    }
}

// ---------------------------------------------------------------------------
// Kernel 2: causal flash attention on tensor cores (tf32), scale = 1/sqrt(S).
// grid = (16 qtiles reversed, 128 bh), 256 threads = 8 warps (4m x 2n),
// warp = 16x32. (Round-12 proven version, unchanged.)
// ---------------------------------------------------------------------------
#define F_KSM 4096
#define F_VSM 12800
#define F_PSM 22016
#define F_REDM 26112
#define F_REDS 26240
#define F_WORDS 26368
#define F_BYTES (F_WORDS*4)

__global__ __launch_bounds__(256, 2) void flash_kernel()
{
    extern __shared__ unsigned fsm[];
    unsigned* qsm = fsm;
    unsigned* ksm = fsm + F_KSM;     // 2 bufs, stride 4352 ([seq][d] stride 68)
    unsigned* vsm = fsm + F_VSM;     // 2 bufs, stride 4608 ([seq][d] stride 72)
    unsigned* psm = fsm + F_PSM;
    float* redm   = (float*)(fsm + F_REDM);   // [2][64]
    float* reds   = (float*)(fsm + F_REDS);   // [2][64]

    const int qt = STILES - 1 - blockIdx.x;   // heavy qtiles first
    const int bh = blockIdx.y;
    const int b  = bh >> 4;
    const int h  = bh & 15;

    const float* qb = g_q + (size_t)bh * SS * DD;
    const float* kb = g_k + (size_t)bh * SS * DD;
    const float* vb = g_v + (size_t)bh * SS * DD;

    const int tid  = threadIdx.x;
    const int lane = tid & 31, wid = tid >> 5;
    const int g = lane >> 2, t = lane & 3;
    const int wm2 = wid >> 1, wn2 = wid & 1;
    const int r0  = wm2 * 16 + g;
    const int swL = (r0 >> 1) & 3;
    const int swH = ((r0 + 8) >> 1) & 3;

    const unsigned kbase_u = (unsigned)__cvta_generic_to_shared(ksm);
    const unsigned vbase_u = (unsigned)__cvta_generic_to_shared(vsm);

    const float scale = 0.031622776601683794f;  // 1/sqrt(1000)
    const float NEG_INF = __int_as_float(0xff800000);

    #define ISSUE_KV(j, bf_) do {                                           \
        _Pragma("unroll")                                                   \
        for (int p = 0; p < 4; p++) {                                       \
            const int idx = p * 256 + tid;                                  \
            const int rr  = idx >> 4;                                       \
            const int dq  = (idx & 15) * 4;                                 \
            const int gs  = (j) * 64 + rr;                                  \
            const int pr  = (gs < SS) ? 16 : 0;                             \
            const int gc  = (gs < SS) ? gs : 0;                             \
            cp16z(kbase_u + (unsigned)((bf_) * 4352 + rr * 68 + dq) * 4u,   \
                  kb + (size_t)gc * DD + dq, pr);                           \
            cp16z(vbase_u + (unsigned)((bf_) * 4608 + rr * 72 + dq) * 4u,   \
                  vb + (size_t)gc * DD + dq, pr);                           \
        }                                                                   \
    } while (0)

    // ---- Q fill (raw bits: g_q is pre-rounded tf32)
    {
        const int row = tid >> 2, slab = tid & 3;
        const int gs = qt * 64 + row;
        unsigned f[16];
        if (gs < SS) {
            const float* p = qb + (size_t)gs * DD + slab * 16;
            #pragma unroll
            for (int q = 0; q < 4; q++) {
                uint4 v = *(const uint4*)(p + q * 4);
                f[q*4+0]=v.x; f[q*4+1]=v.y; f[q*4+2]=v.z; f[q*4+3]=v.w;
            }
        } else {
            #pragma unroll
            for (int i = 0; i < 16; i++) f[i] = 0u;
        }
        const int sw = (row >> 1) & 3;
        unsigned* base = qsm + (row * 4 + slab) * 16;
        #pragma unroll
        for (int c = 0; c < 4; c++) {
            uint4 u;
            u.x = f[c];     u.y = f[4 + c];
            u.z = f[8 + c]; u.w = f[12 + c];
            *(uint4*)(base + ((c ^ sw) << 2)) = u;
        }
    }

    // prefetch KV(0)
    ISSUE_KV(0, 0);
    cp_commit();

    float oacc[4][4] = {};
    float mrow[2] = {NEG_INF, NEG_INF};
    float lrow[2] = {0.f, 0.f};

    for (int jt = 0; jt <= qt; jt++) {
        const int buf = jt & 1;
        cp_wait0();
        __syncthreads();   // KV(jt) visible; guards psm/red/Q and buf reuse
        if (jt < qt) { ISSUE_KV(jt + 1, buf ^ 1); cp_commit(); }

        const unsigned* kbuf = ksm + buf * 4352;
        const unsigned* vbuf = vsm + buf * 4608;

        // ---- S = Q @ K^T
        float sacc[4][4] = {};
        #pragma unroll
        for (int s = 0; s < 4; s++) {
            uint4 alo = *(const uint4*)(qsm + (r0 * 4 + s) * 16 + ((t ^ swL) << 2));
            uint4 ahi = *(const uint4*)(qsm + ((r0 + 8) * 4 + s) * 16 + ((t ^ swH) << 2));
            unsigned a1[4] = {alo.x, ahi.x, alo.y, ahi.y};
            unsigned a2[4] = {alo.z, ahi.z, alo.w, ahi.w};
            #pragma unroll
            for (int nt = 0; nt < 4; nt++) {
                const int col = wn2 * 32 + nt * 8 + g;
                const unsigned* kp = kbuf + col * 68 + s * 16;
                unsigned b1[2] = {kp[t],     kp[t + 4]};
                unsigned b2[2] = {kp[t + 8], kp[t + 12]};
                mma8(sacc[nt], a1, b1);
                mma8(sacc[nt], a2, b2);
            }
        }

        // ---- scale + causal mask (diagonal tile only)
        if (jt == qt) {
            #pragma unroll
            for (int nt = 0; nt < 4; nt++) {
                #pragma unroll
                for (int e = 0; e < 4; e++) {
                    const int grow = qt * 64 + r0 + (e >> 1) * 8;
                    const int gcol = jt * 64 + wn2 * 32 + nt * 8 + 2 * t + (e & 1);
                    sacc[nt][e] = (gcol > grow || gcol >= SS) ? NEG_INF
                                                              : sacc[nt][e] * scale;
                }
            }
        } else {
            #pragma unroll
            for (int nt = 0; nt < 4; nt++)
                #pragma unroll
                for (int e = 0; e < 4; e++)
                    sacc[nt][e] *= scale;
        }

        // ---- row max (warp part), cross-warp via smem
        #pragma unroll
        for (int rr = 0; rr < 2; rr++) {
            float v = fmaxf(fmaxf(sacc[0][rr*2], sacc[0][rr*2+1]),
                            fmaxf(sacc[1][rr*2], sacc[1][rr*2+1]));
            v = fmaxf(v, fmaxf(fmaxf(sacc[2][rr*2], sacc[2][rr*2+1]),
                               fmaxf(sacc[3][rr*2], sacc[3][rr*2+1])));
            v = fmaxf(v, __shfl_xor_sync(0xffffffffu, v, 1));
            v = fmaxf(v, __shfl_xor_sync(0xffffffffu, v, 2));
            if (t == 0) redm[wn2 * 64 + r0 + rr * 8] = v;
        }
        __syncthreads();

        // ---- exp, P -> psm (RNA, A-layout), partial sums, rescale O
        float alpha[2];
        #pragma unroll
        for (int rr = 0; rr < 2; rr++) {
            const int rl = r0 + rr * 8;
            const float mtile = fmaxf(redm[rl], redm[64 + rl]);
            const float mnew  = fmaxf(mrow[rr], mtile);
            alpha[rr] = __expf(mrow[rr] - mnew);
            mrow[rr]  = mnew;
            float sum = 0.f;
            const int sw = (rl >> 1) & 3;
            unsigned* pbase = psm + rl * 64;
            #pragma unroll
            for (int nt = 0; nt < 4; nt++) {
                #pragma unroll
                for (int e = 0; e < 2; e++) {
                    const float pv = __expf(sacc[nt][rr * 2 + e] - mnew);
                    sum += pv;
                    const int col  = wn2 * 32 + nt * 8 + 2 * t + e;
                    const int slab = col >> 4, cc = col & 3, j = (col >> 2) & 3;
                    pbase[slab * 16 + ((cc ^ sw) << 2) + j] = f2tf(pv);
                }
                oacc[nt][rr * 2]     *= alpha[rr];
                oacc[nt][rr * 2 + 1] *= alpha[rr];
            }
            sum += __shfl_xor_sync(0xffffffffu, sum, 1);
            sum += __shfl_xor_sync(0xffffffffu, sum, 2);
            if (t == 0) reds[wn2 * 64 + rl] = sum;
        }
        __syncthreads();

        #pragma unroll
        for (int rr = 0; rr < 2; rr++) {
            const int rl = r0 + rr * 8;
            lrow[rr] = lrow[rr] * alpha[rr] + reds[rl] + reds[64 + rl];
        }

        // ---- O += P @ V
        #pragma unroll
        for (int s = 0; s < 4; s++) {
            uint4 alo = *(const uint4*)(psm + (r0 * 4 + s) * 16 + ((t ^ swL) << 2));
            uint4 ahi = *(const uint4*)(psm + ((r0 + 8) * 4 + s) * 16 + ((t ^ swH) << 2));
            unsigned a1[4] = {alo.x, ahi.x, alo.y, ahi.y};
            unsigned a2[4] = {alo.z, ahi.z, alo.w, ahi.w};
            #pragma unroll
            for (int nt = 0; nt < 4; nt++) {
                const int col = wn2 * 32 + nt * 8 + g;
                const unsigned* vp = vbuf + (s * 16) * 72 + col;
                unsigned b1[2] = {vp[t * 72],       vp[(t + 4) * 72]};
                unsigned b2[2] = {vp[(t + 8) * 72], vp[(t + 12) * 72]};
                mma8(oacc[nt], a1, b1);
                mma8(oacc[nt], a2, b2);
            }
        }
    }

    // ---- write y[b, s, h*64 + d], tf32-prerounded for proj's raw loads
    #pragma unroll
    for (int rr = 0; rr < 2; rr++) {
        const int grow = qt * 64 + r0 + rr * 8;
        if (grow < SS) {
            const float inv = 1.f / lrow[rr];
            #pragma unroll
            for (int nt = 0; nt < 4; nt++) {
                float2 r;
                r.x = f2tf_f(oacc[nt][rr * 2]     * inv);
                r.y = f2tf_f(oacc[nt][rr * 2 + 1] * inv);
                const int col = wn2 * 32 + nt * 8 + 2 * t;
                *(float2*)&g_y[((size_t)b * SS + grow) * EE + h * DD + col] = r;
            }
        }
    }
    #undef ISSUE_KV
}

// ---------------------------------------------------------------------------
// Kernel 3: out = GELU(y @ wp + bp). grid = (8 ntiles, 63 mtiles)
// ---------------------------------------------------------------------------
__global__ __launch_bounds__(256, 2) void proj_gelu_kernel(
    const float* __restrict__ bp, float* __restrict__ out)
{
    extern __shared__ unsigned gsm[];
    unsigned* sA = gsm;
    unsigned* sB = gsm + STAGES * SA_WORDS;

    const int n0 = blockIdx.x * TNn;
    const int m0 = blockIdx.y * TMm;

    BLP bl; bl.wp = g_wp; bl.n0 = n0;

    float acc[4][4][4] = {};
    gemm_core(g_y, m0, bl, sA, sB, acc);

    const int tid  = threadIdx.x;
    const int lane = tid & 31, wid = tid >> 5;
    const int g = lane >> 2, t = lane & 3;
    const int wm = wid >> 2, wn = wid & 3;

    #pragma unroll
    for (int nt = 0; nt < 4; nt++) {
        const int col = n0 + wn * 32 + nt * 8 + 2 * t;
        const float bi0 = bp[col];
        const float bi1 = bp[col + 1];
        #pragma unroll
        for (int mt = 0; mt < 4; mt++) {
            #pragma unroll
            for (int half = 0; half < 2; half++) {
                const int m = m0 + wm * 64 + mt * 16 + g + half * 8;
                if (m < MM) {
                    float t0 = acc[mt][nt][half * 2 + 0] + bi0;
                    float t1 = acc[mt][nt][half * 2 + 1] + bi1;
                    float2 r;
                    r.x = 0.5f * t0 * (1.0f + erff(t0 * 0.70710678118654752f));
                    r.y = 0.5f * t1 * (1.0f + erff(t1 * 0.70710678118654752f));
                    *(float2*)&out[(size_t)m * EE + col] = r;
                }
            }
        }
    }
}

// ---------------------------------------------------------------------------
extern "C" void kernel_launch(void* const* d_in, const int* in_sizes, int n_in,
                              void* d_out, int out_size)
{
    const float* x  = (const float*)d_in[0];
    const float* wq = (const float*)d_in[1];
    const float* bq = (const float*)d_in[2];
    const float* wk = (const float*)d_in[3];
    const float* bk = (const float*)d_in[4];
    const float* wv = (const float*)d_in[5];
    const float* bv = (const float*)d_in[6];
    const float* wp = (const float*)d_in[7];
    const float* bp = (const float*)d_in[8];
    float* out = (float*)d_out;

    cudaFuncSetAttribute(qkv_gemm_kernel,
                         cudaFuncAttributeMaxDynamicSharedMemorySize, GEMM_SMEM_BYTES);
    cudaFuncSetAttribute(proj_gelu_kernel,
                         cudaFuncAttributeMaxDynamicSharedMemorySize, GEMM_SMEM_BYTES);
    cudaFuncSetAttribute(flash_kernel,
                         cudaFuncAttributeMaxDynamicSharedMemorySize, F_BYTES);

    // Fused pre-round of inputs/weights to tf32 (RNA), one launch
    preround_all<<<4096, 256>>>(x, wq, wk, wv, wp);

    // Unified QKV projection (tensor core TF32, 3-stage TKk=32 cp.async)
    dim3 g1(3 * EE / TNn, MT);     // (24, 63)
    qkv_gemm_kernel<<<g1, 256, GEMM_SMEM_BYTES>>>(bq, bk, bv);

    // Flash attention (round-12 version, heavy qtiles scheduled first)
    dim3 g2(STILES, BB * HH);      // (16, 128)
    flash_kernel<<<g2, 256, F_BYTES>>>();

    // Output projection + GELU
    dim3 g3(EE / TNn, MT);         // (8, 63)
    proj_gelu_kernel<<<g3, 256, GEMM_SMEM_BYTES>>>(bp, out);
}

// round 17
// speedup vs baseline: 1.4487x; 1.0152x over previous
#include <cuda_runtime.h>
#include <math.h>

#define BB 8
#define SS 1000
#define EE 1024
#define HH 16
#define DD 64
#define MM (BB*SS)        // 8000
#define STILES 16

#define TMm 128
#define TNn 128
#define TKk 32
#define NITER (EE/TKk)    // 32
#define MT ((MM + TMm - 1)/TMm)   // 63
#define STAGES 3

// Scratch (allocation-free rule: __device__ globals)
__device__ float g_q[BB*HH*SS*DD];
__device__ float g_k[BB*HH*SS*DD];
__device__ float g_v[BB*HH*SS*DD];
__device__ float g_y[BB*SS*EE];
// tf32-prerounded WEIGHT copies (weight-side RNA is the only rounding that
// matters for rel_err; x / K / V raw-truncate losslessly w.r.t. the metric)
__device__ float g_wq[HH*EE*DD];
__device__ float g_wk[HH*EE*DD];
__device__ float g_wv[HH*EE*DD];
__device__ float g_wp[EE*EE];

// ---------------------------------------------------------------------------
// helpers
// ---------------------------------------------------------------------------
__device__ __forceinline__ unsigned f2tf(float f) {
    unsigned u;
    asm("cvt.rna.tf32.f32 %0, %1;" : "=r"(u) : "f"(f));
    return u;
}
__device__ __forceinline__ float f2tf_f(float f) {
    return __uint_as_float(f2tf(f));
}

__device__ __forceinline__ void mma8(float* d, const unsigned* a, const unsigned* b) {
    asm volatile(
        "mma.sync.aligned.m16n8k8.row.col.f32.tf32.tf32.f32 "
        "{%0,%1,%2,%3}, {%4,%5,%6,%7}, {%8,%9}, {%0,%1,%2,%3};"
        : "+f"(d[0]), "+f"(d[1]), "+f"(d[2]), "+f"(d[3])
        : "r"(a[0]), "r"(a[1]), "r"(a[2]), "r"(a[3]),
          "r"(b[0]), "r"(b[1]));
}

// cp.async 16B with src-size predicate (0 -> zero-fill)
__device__ __forceinline__ void cp16z(unsigned saddr, const void* gsrc, int pred16) {
    asm volatile("cp.async.cg.shared.global [%0], [%1], 16, %2;\n"
                 :: "r"(saddr), "l"(gsrc), "r"(pred16));
}
__device__ __forceinline__ void cp_commit() {
    asm volatile("cp.async.commit_group;\n" ::);
}
__device__ __forceinline__ void cp_wait1() {
    asm volatile("cp.async.wait_group 1;\n" ::);
}
__device__ __forceinline__ void cp_wait0() {
    asm volatile("cp.async.wait_group 0;\n" ::);
}

// ---------------------------------------------------------------------------
// Kernel 0: fused tf32 pre-round (RNA) of the WEIGHTS only (one launch)
// ---------------------------------------------------------------------------
#define N4_W (HH*EE*DD/4)     // 262144
#define N4_P (EE*EE/4)        // 262144
#define N4_TOTAL (3*N4_W + N4_P)   // 1048576

__global__ __launch_bounds__(256) void preround_all(
    const float* __restrict__ wq, const float* __restrict__ wk,
    const float* __restrict__ wv, const float* __restrict__ wp)
{
    int i = blockIdx.x * blockDim.x + threadIdx.x;
    const int stride = gridDim.x * blockDim.x;
    for (; i < N4_TOTAL; i += stride) {
        const float4* s;
        float* dbase;
        int off;
        if (i < N4_W)               { off = i;            s = (const float4*)wq + off; dbase = g_wq; }
        else if (i < 2*N4_W)        { off = i -   N4_W;   s = (const float4*)wk + off; dbase = g_wk; }
        else if (i < 3*N4_W)        { off = i - 2*N4_W;   s = (const float4*)wv + off; dbase = g_wv; }
        else                        { off = i - 3*N4_W;   s = (const float4*)wp + off; dbase = g_wp; }
        float4 v = *s;
        uint4 u;
        u.x = f2tf(v.x); u.y = f2tf(v.y);
        u.z = f2tf(v.z); u.w = f2tf(v.w);
        ((uint4*)dbase)[off] = u;
    }
}

// ---------------------------------------------------------------------------
// 128x128x32 TF32 GEMM core: 8 warps (2m x 4n), 3-stage cp.async (A and B).
// B sources pre-rounded tf32 (exact); A raw fp32 (HW truncation — metric-
// equivalent per round-7/16 evidence).
// ---------------------------------------------------------------------------
#define SA_WORDS 4096
#define SB_STRIDE 136
#define SB_WORDS (32*SB_STRIDE)   // 4352
#define GEMM_SMEM_WORDS (STAGES*(SA_WORDS+SB_WORDS))   // 25344
#define GEMM_SMEM_BYTES (GEMM_SMEM_WORDS*4)            // 101376

struct BLQKV {
    const float* w;   // [H][E][D], pre-rounded
    int n0;
    __device__ __forceinline__ const float* addr(int k, int nq) const {
        int n = n0 + nq * 4;
        int h = n >> 6;
        int d = n & 63;
        return &w[((size_t)h * EE + k) * DD + d];
    }
};

struct BLP {
    const float* wp;  // [E, E], pre-rounded
    int n0;
    __device__ __forceinline__ const float* addr(int k, int nq) const {
        return &wp[(size_t)k * EE + n0 + nq * 4];
    }
};

template<class BL>
__device__ __forceinline__ void gemm_core(
    const float* __restrict__ Ag, int m0, const BL& bl,
    unsigned* sA, unsigned* sB, float acc[4][4][4])
{
    const int tid  = threadIdx.x;
    const int lane = tid & 31, wid = tid >> 5;
    const int g = lane >> 2, t = lane & 3;
    const int wm = wid >> 2, wn = wid & 3;

    // A producer: thread -> (row = tid>>1, half ah = tid&1), 4 x 16B chunks
    const int arow = tid >> 1, ah = tid & 1;
    const int am   = m0 + arow;
    const int sw3p = ((arow >> 1) & 3) | ((arow & 1) << 2);
    const int apred = (am < MM) ? 16 : 0;
    const float* asrc = Ag + (size_t)(am < MM ? am : 0) * EE + ah * 16;

    const unsigned sAu = (unsigned)__cvta_generic_to_shared(sA);
    const unsigned sBu = (unsigned)__cvta_generic_to_shared(sB);
    unsigned adst[4];
    #pragma unroll
    for (int j = 0; j < 4; j++)
        adst[j] = (unsigned)(arow * 32 + ((((ah << 2) + j) ^ sw3p) << 2)) * 4u;

    // B producer: thread -> (k = tid>>3, n-quads tid&7 + {0,8,16,24})
    const int bk  = tid >> 3;
    const int bq0 = tid & 7;
    unsigned bdst[4];
    #pragma unroll
    for (int q = 0; q < 4; q++)
        bdst[q] = (unsigned)(bk * SB_STRIDE + (bq0 + 8 * q) * 4) * 4u;

    #define ISSUE_AB(it, st) do {                                           \
        const float* s_ = asrc + (it) * TKk;                                \
        const unsigned ab_ = sAu + (unsigned)(st) * (SA_WORDS * 4u);        \
        _Pragma("unroll")                                                   \
        for (int j = 0; j < 4; j++)                                         \
            cp16z(ab_ + adst[j], s_ + 4 * j, apred);                        \
        const unsigned bb_ = sBu + (unsigned)(st) * (SB_WORDS * 4u);        \
        _Pragma("unroll")                                                   \
        for (int q = 0; q < 4; q++)                                         \
            cp16z(bb_ + bdst[q], bl.addr((it) * TKk + bk, bq0 + 8 * q), 16);\
    } while (0)

    #define GEMM_COMPUTE(st) do {                                          \
        const unsigned* ab_ = sA + (st) * SA_WORDS;                         \
        const unsigned* bbase_ = sB + (st) * SB_WORDS;                      \
        _Pragma("unroll")                                                   \
        for (int s = 0; s < 4; s++) {                                       \
            unsigned bf[4][2];                                              \
            _Pragma("unroll")                                               \
            for (int nt = 0; nt < 4; nt++) {                                \
                const unsigned* b_ = bbase_ + wn * 32 + nt * 8 + g;         \
                bf[nt][0] = b_[(8 * s + t)     * SB_STRIDE];                \
                bf[nt][1] = b_[(8 * s + t + 4) * SB_STRIDE];                \
            }                                                               \
            _Pragma("unroll")                                               \
            for (int mt = 0; mt < 4; mt++) {                                \
                const int r_ = wm * 64 + mt * 16 + g;                       \
                const int sw3_ = ((r_ >> 1) & 3) | ((r_ & 1) << 2);         \
                const unsigned* p1 = ab_ + r_ * 32 + t;                     \
                const unsigned* p2 = p1 + 8 * 32;                           \
                const int c0 = (((2 * s)     ^ sw3_) << 2);                 \
                const int c1 = (((2 * s + 1) ^ sw3_) << 2);                 \
                unsigned a_[4] = {p1[c0], p2[c0], p1[c1], p2[c1]};          \
                _Pragma("unroll")                                           \
                for (int nt = 0; nt < 4; nt++)                              \
                    mma8(acc[mt][nt], a_, bf[nt]);                          \
            }                                                               \
        }                                                                   \
    } while (0)

    // prologue: 2 stages in flight
    ISSUE_AB(0, 0); cp_commit();
    ISSUE_AB(1, 1); cp_commit();

    int st = 0;
    for (int it = 0; it < NITER; it++) {
        cp_wait1();
        __syncthreads();             // stage(it) visible to all warps
        GEMM_COMPUTE(st);
        if (it + 2 < NITER) {
            int st2 = st + 2; if (st2 >= STAGES) st2 -= STAGES;
            ISSUE_AB(it + 2, st2);
        }
        cp_commit();                 // possibly-empty group keeps wait count
        if (++st == STAGES) st = 0;
    }

    #undef ISSUE_AB
    #undef GEMM_COMPUTE
}

// ---------------------------------------------------------------------------
// Kernel 1: unified QKV projection. grid = (24 ntiles over 3072, 63 mtiles)
// A-side reads x directly (no pre-round).
// ---------------------------------------------------------------------------
__global__ __launch_bounds__(256, 2) void qkv_gemm_kernel(
    const float* __restrict__ x,
    const float* __restrict__ bq, const float* __restrict__ bk_,
    const float* __restrict__ bv)
{
    extern __shared__ unsigned gsm[];
    unsigned* sA = gsm;
    unsigned* sB = gsm + STAGES * SA_WORDS;

    const int n0g   = blockIdx.x * TNn;
    const int which = n0g >> 10;
    const int n0    = n0g & 1023;
    const int m0    = blockIdx.y * TMm;

    const float* ws[3]    = {g_wq, g_wk, g_wv};
    const float* bias3[3] = {bq, bk_, bv};
    float* outs[3]        = {g_q, g_k, g_v};
    const float* bias = bias3[which];
    float* out        = outs[which];

    BLQKV bl; bl.w = ws[which]; bl.n0 = n0;

    float acc[4][4][4] = {};
    gemm_core(x, m0, bl, sA, sB, acc);

    const int tid  = threadIdx.x;
    const int lane = tid & 31, wid = tid >> 5;
    const int g = lane >> 2, t = lane & 3;
    const int wm = wid >> 2, wn = wid & 3;

    #pragma unroll
    for (int nt = 0; nt < 4; nt++) {
        const int nc = n0 + wn * 32 + nt * 8 + 2 * t;
        const int h  = nc >> 6;
        const int d  = nc & 63;
        const float bi0 = bias[h * DD + d];
        const float bi1 = bias[h * DD + d + 1];
        #pragma unroll
        for (int mt = 0; mt < 4; mt++) {
            #pragma unroll
            for (int half = 0; half < 2; half++) {
                const int m = m0 + wm * 64 + mt * 16 + g + half * 8;
                if (m < MM) {
                    const int b = m / SS, s = m % SS;
                    float2 r;
                    r.x = f2tf_f(acc[mt][nt][half * 2 + 0] + bi0);
                    r.y = f2tf_f(acc[mt][nt][half * 2 + 1] + bi1);
                    *(float2*)&out[((size_t)(b * HH + h) * SS + s) * DD + d] = r;
                }
            }
        }
    }
}

// ---------------------------------------------------------------------------
// Kernel 2: causal flash attention on tensor cores (tf32), scale = 1/sqrt(S).
// grid = (16 qtiles reversed, 128 bh), 256 threads = 8 warps (4m x 2n),
// warp = 16x32. (Round-12 proven version, unchanged.)
// ---------------------------------------------------------------------------
#define F_KSM 4096
#define F_VSM 12800
#define F_PSM 22016
#define F_REDM 26112
#define F_REDS 26240
#define F_WORDS 26368
#define F_BYTES (F_WORDS*4)

__global__ __launch_bounds__(256, 2) void flash_kernel()
{
    extern __shared__ unsigned fsm[];
    unsigned* qsm = fsm;
    unsigned* ksm = fsm + F_KSM;     // 2 bufs, stride 4352 ([seq][d] stride 68)
    unsigned* vsm = fsm + F_VSM;     // 2 bufs, stride 4608 ([seq][d] stride 72)
    unsigned* psm = fsm + F_PSM;
    float* redm   = (float*)(fsm + F_REDM);   // [2][64]
    float* reds   = (float*)(fsm + F_REDS);   // [2][64]

    const int qt = STILES - 1 - blockIdx.x;   // heavy qtiles first
    const int bh = blockIdx.y;
    const int b  = bh >> 4;
    const int h  = bh & 15;

    const float* qb = g_q + (size_t)bh * SS * DD;
    const float* kb = g_k + (size_t)bh * SS * DD;
    const float* vb = g_v + (size_t)bh * SS * DD;

    const int tid  = threadIdx.x;
    const int lane = tid & 31, wid = tid >> 5;
    const int g = lane >> 2, t = lane & 3;
    const int wm2 = wid >> 1, wn2 = wid & 1;
    const int r0  = wm2 * 16 + g;
    const int swL = (r0 >> 1) & 3;
    const int swH = ((r0 + 8) >> 1) & 3;

    const unsigned kbase_u = (unsigned)__cvta_generic_to_shared(ksm);
    const unsigned vbase_u = (unsigned)__cvta_generic_to_shared(vsm);

    const float scale = 0.031622776601683794f;  // 1/sqrt(1000)
    const float NEG_INF = __int_as_float(0xff800000);

    #define ISSUE_KV(j, bf_) do {                                           \
        _Pragma("unroll")                                                   \
        for (int p = 0; p < 4; p++) {                                       \
            const int idx = p * 256 + tid;                                  \
            const int rr  = idx >> 4;                                       \
            const int dq  = (idx & 15) * 4;                                 \
            const int gs  = (j) * 64 + rr;                                  \
            const int pr  = (gs < SS) ? 16 : 0;                             \
            const int gc  = (gs < SS) ? gs : 0;                             \
            cp16z(kbase_u + (unsigned)((bf_) * 4352 + rr * 68 + dq) * 4u,   \
                  kb + (size_t)gc * DD + dq, pr);                           \
            cp16z(vbase_u + (unsigned)((bf_) * 4608 + rr * 72 + dq) * 4u,   \
                  vb + (size_t)gc * DD + dq, pr);                           \
        }                                                                   \
    } while (0)

    // ---- Q fill (raw bits: g_q is RNA-rounded at the QKV epilogue)
    {
        const int row = tid >> 2, slab = tid & 3;
        const int gs = qt * 64 + row;
        unsigned f[16];
        if (gs < SS) {
            const float* p = qb + (size_t)gs * DD + slab * 16;
            #pragma unroll
            for (int q = 0; q < 4; q++) {
                uint4 v = *(const uint4*)(p + q * 4);
                f[q*4+0]=v.x; f[q*4+1]=v.y; f[q*4+2]=v.z; f[q*4+3]=v.w;
            }
        } else {
            #pragma unroll
            for (int i = 0; i < 16; i++) f[i] = 0u;
        }
        const int sw = (row >> 1) & 3;
        unsigned* base = qsm + (row * 4 + slab) * 16;
        #pragma unroll
        for (int c = 0; c < 4; c++) {
            uint4 u;
            u.x = f[c];     u.y = f[4 + c];
            u.z = f[8 + c]; u.w = f[12 + c];
            *(uint4*)(base + ((c ^ sw) << 2)) = u;
        }
    }

    // prefetch KV(0)
    ISSUE_KV(0, 0);
    cp_commit();

    float oacc[4][4] = {};
    float mrow[2] = {NEG_INF, NEG_INF};
    float lrow[2] = {0.f, 0.f};

    for (int jt = 0; jt <= qt; jt++) {
        const int buf = jt & 1;
        cp_wait0();
        __syncthreads();   // KV(jt) visible; guards psm/red/Q and buf reuse
        if (jt < qt) { ISSUE_KV(jt + 1, buf ^ 1); cp_commit(); }

        const unsigned* kbuf = ksm + buf * 4352;
        const unsigned* vbuf = vsm + buf * 4608;

        // ---- S = Q @ K^T
        float sacc[4][4] = {};
        #pragma unroll
        for (int s = 0; s < 4; s++) {
            uint4 alo = *(const uint4*)(qsm + (r0 * 4 + s) * 16 + ((t ^ swL) << 2));
            uint4 ahi = *(const uint4*)(qsm + ((r0 + 8) * 4 + s) * 16 + ((t ^ swH) << 2));
            unsigned a1[4] = {alo.x, ahi.x, alo.y, ahi.y};
            unsigned a2[4] = {alo.z, ahi.z, alo.w, ahi.w};
            #pragma unroll
            for (int nt = 0; nt < 4; nt++) {
                const int col = wn2 * 32 + nt * 8 + g;
                const unsigned* kp = kbuf + col * 68 + s * 16;
                unsigned b1[2] = {kp[t],     kp[t + 4]};
                unsigned b2[2] = {kp[t + 8], kp[t + 12]};
                mma8(sacc[nt], a1, b1);
                mma8(sacc[nt], a2, b2);
            }
        }

        // ---- scale + causal mask (diagonal tile only)
        if (jt == qt) {
            #pragma unroll
            for (int nt = 0; nt < 4; nt++) {
                #pragma unroll
                for (int e = 0; e < 4; e++) {
                    const int grow = qt * 64 + r0 + (e >> 1) * 8;
                    const int gcol = jt * 64 + wn2 * 32 + nt * 8 + 2 * t + (e & 1);
                    sacc[nt][e] = (gcol > grow || gcol >= SS) ? NEG_INF
                                                              : sacc[nt][e] * scale;
                }
            }
        } else {
            #pragma unroll
            for (int nt = 0; nt < 4; nt++)
                #pragma unroll
                for (int e = 0; e < 4; e++)
                    sacc[nt][e] *= scale;
        }

        // ---- row max (warp part), cross-warp via smem
        #pragma unroll
        for (int rr = 0; rr < 2; rr++) {
            float v = fmaxf(fmaxf(sacc[0][rr*2], sacc[0][rr*2+1]),
                            fmaxf(sacc[1][rr*2], sacc[1][rr*2+1]));
            v = fmaxf(v, fmaxf(fmaxf(sacc[2][rr*2], sacc[2][rr*2+1]),
                               fmaxf(sacc[3][rr*2], sacc[3][rr*2+1])));
            v = fmaxf(v, __shfl_xor_sync(0xffffffffu, v, 1));
            v = fmaxf(v, __shfl_xor_sync(0xffffffffu, v, 2));
            if (t == 0) redm[wn2 * 64 + r0 + rr * 8] = v;
        }
        __syncthreads();

        // ---- exp, P -> psm (RNA, A-layout), partial sums, rescale O
        float alpha[2];
        #pragma unroll
        for (int rr = 0; rr < 2; rr++) {
            const int rl = r0 + rr * 8;
            const float mtile = fmaxf(redm[rl], redm[64 + rl]);
            const float mnew  = fmaxf(mrow[rr], mtile);
            alpha[rr] = __expf(mrow[rr] - mnew);
            mrow[rr]  = mnew;
            float sum = 0.f;
            const int sw = (rl >> 1) & 3;
            unsigned* pbase = psm + rl * 64;
            #pragma unroll
            for (int nt = 0; nt < 4; nt++) {
                #pragma unroll
                for (int e = 0; e < 2; e++) {
                    const float pv = __expf(sacc[nt][rr * 2 + e] - mnew);
                    sum += pv;
                    const int col  = wn2 * 32 + nt * 8 + 2 * t + e;
                    const int slab = col >> 4, cc = col & 3, j = (col >> 2) & 3;
                    pbase[slab * 16 + ((cc ^ sw) << 2) + j] = f2tf(pv);
                }
                oacc[nt][rr * 2]     *= alpha[rr];
                oacc[nt][rr * 2 + 1] *= alpha[rr];
            }
            sum += __shfl_xor_sync(0xffffffffu, sum, 1);
            sum += __shfl_xor_sync(0xffffffffu, sum, 2);
            if (t == 0) reds[wn2 * 64 + rl] = sum;
        }
        __syncthreads();

        #pragma unroll
        for (int rr = 0; rr < 2; rr++) {
            const int rl = r0 + rr * 8;
            lrow[rr] = lrow[rr] * alpha[rr] + reds[rl] + reds[64 + rl];
        }

        // ---- O += P @ V
        #pragma unroll
        for (int s = 0; s < 4; s++) {
            uint4 alo = *(const uint4*)(psm + (r0 * 4 + s) * 16 + ((t ^ swL) << 2));
            uint4 ahi = *(const uint4*)(psm + ((r0 + 8) * 4 + s) * 16 + ((t ^ swH) << 2));
            unsigned a1[4] = {alo.x, ahi.x, alo.y, ahi.y};
            unsigned a2[4] = {alo.z, ahi.z, alo.w, ahi.w};
            #pragma unroll
            for (int nt = 0; nt < 4; nt++) {
                const int col = wn2 * 32 + nt * 8 + g;
                const unsigned* vp = vbuf + (s * 16) * 72 + col;
                unsigned b1[2] = {vp[t * 72],       vp[(t + 4) * 72]};
                unsigned b2[2] = {vp[(t + 8) * 72], vp[(t + 12) * 72]};
                mma8(oacc[nt], a1, b1);
                mma8(oacc[nt], a2, b2);
            }
        }
    }

    // ---- write y[b, s, h*64 + d], RNA-rounded for proj's raw loads
    #pragma unroll
    for (int rr = 0; rr < 2; rr++) {
        const int grow = qt * 64 + r0 + rr * 8;
        if (grow < SS) {
            const float inv = 1.f / lrow[rr];
            #pragma unroll
            for (int nt = 0; nt < 4; nt++) {
                float2 r;
                r.x = f2tf_f(oacc[nt][rr * 2]     * inv);
                r.y = f2tf_f(oacc[nt][rr * 2 + 1] * inv);
                const int col = wn2 * 32 + nt * 8 + 2 * t;
                *(float2*)&g_y[((size_t)b * SS + grow) * EE + h * DD + col] = r;
            }
        }
    }
    #undef ISSUE_KV
}

// ---------------------------------------------------------------------------
// Kernel 3: out = GELU(y @ wp + bp). grid = (8 ntiles, 63 mtiles)
// ---------------------------------------------------------------------------
__global__ __launch_bounds__(256, 2) void proj_gelu_kernel(
    const float* __restrict__ bp, float* __restrict__ out)
{
    extern __shared__ unsigned gsm[];
    unsigned* sA = gsm;
    unsigned* sB = gsm + STAGES * SA_WORDS;

    const int n0 = blockIdx.x * TNn;
    const int m0 = blockIdx.y * TMm;

    BLP bl; bl.wp = g_wp; bl.n0 = n0;

    float acc[4][4][4] = {};
    gemm_core(g_y, m0, bl, sA, sB, acc);

    const int tid  = threadIdx.x;
    const int lane = tid & 31, wid = tid >> 5;
    const int g = lane >> 2, t = lane & 3;
    const int wm = wid >> 2, wn = wid & 3;

    #pragma unroll
    for (int nt = 0; nt < 4; nt++) {
        const int col = n0 + wn * 32 + nt * 8 + 2 * t;
        const float bi0 = bp[col];
        const float bi1 = bp[col + 1];
        #pragma unroll
        for (int mt = 0; mt < 4; mt++) {
            #pragma unroll
            for (int half = 0; half < 2; half++) {
                const int m = m0 + wm * 64 + mt * 16 + g + half * 8;
                if (m < MM) {
                    float t0 = acc[mt][nt][half * 2 + 0] + bi0;
                    float t1 = acc[mt][nt][half * 2 + 1] + bi1;
                    float2 r;
                    r.x = 0.5f * t0 * (1.0f + erff(t0 * 0.70710678118654752f));
                    r.y = 0.5f * t1 * (1.0f + erff(t1 * 0.70710678118654752f));
                    *(float2*)&out[(size_t)m * EE + col] = r;
                }
            }
        }
    }
}

// ---------------------------------------------------------------------------
extern "C" void kernel_launch(void* const* d_in, const int* in_sizes, int n_in,
                              void* d_out, int out_size)
{
    const float* x  = (const float*)d_in[0];
    const float* wq = (const float*)d_in[1];
    const float* bq = (const float*)d_in[2];
    const float* wk = (const float*)d_in[3];
    const float* bk = (const float*)d_in[4];
    const float* wv = (const float*)d_in[5];
    const float* bv = (const float*)d_in[6];
    const float* wp = (const float*)d_in[7];
    const float* bp = (const float*)d_in[8];
    float* out = (float*)d_out;

    cudaFuncSetAttribute(qkv_gemm_kernel,
                         cudaFuncAttributeMaxDynamicSharedMemorySize, GEMM_SMEM_BYTES);
    cudaFuncSetAttribute(proj_gelu_kernel,
                         cudaFuncAttributeMaxDynamicSharedMemorySize, GEMM_SMEM_BYTES);
    cudaFuncSetAttribute(flash_kernel,
                         cudaFuncAttributeMaxDynamicSharedMemorySize, F_BYTES);

    // Pre-round WEIGHTS only to tf32 (RNA), one small launch
    preround_all<<<2048, 256>>>(wq, wk, wv, wp);

    // Unified QKV projection (A-side reads x directly)
    dim3 g1(3 * EE / TNn, MT);     // (24, 63)
    qkv_gemm_kernel<<<g1, 256, GEMM_SMEM_BYTES>>>(x, bq, bk, bv);

    // Flash attention (round-12 version, heavy qtiles scheduled first)
    dim3 g2(STILES, BB * HH);      // (16, 128)
    flash_kernel<<<g2, 256, F_BYTES>>>();

    // Output projection + GELU
    dim3 g3(EE / TNn, MT);         // (8, 63)
    proj_gelu_kernel<<<g3, 256, GEMM_SMEM_BYTES>>>(bp, out);
}